// round 3
// baseline (speedup 1.0000x reference)
#include <cuda_runtime.h>
#include <math.h>

#define NSEQ 16130
#define NPAD 16384
#define PADF 254
#define NLM 256
#define DM 512
#define QW 1536
#define HD 64
#define BH 16
#define NTOK 16000
#define NFEAT 16129
#define GR 127

// ---------- static scratch ----------
__device__ float d_h[2ll*NSEQ*DM];
__device__ float d_xln[2ll*NPAD*DM];
__device__ float d_qkv[2ll*NPAD*QW];
__device__ float d_sbuf[(long long)BH*NPAD*NLM];
__device__ float d_ao[2ll*NPAD*DM];
__device__ float d_ql[BH*NLM*HD], d_kl[BH*NLM*HD];
__device__ float d_a2[BH*NLM*NLM], d_z[BH*NLM*NLM], d_z2[BH*NLM*NLM];
__device__ float d_az[BH*NLM*NLM], d_tt[BH*NLM*NLM], d_uu[BH*NLM*NLM];
__device__ float d_t3[BH*NLM*HD], d_w[BH*NLM*HD];
__device__ int d_sc[2];

// ---------- generic tiled SGEMM: C = alpha*A*op(B) (+bias,+relu), batched ----------
template<int TB, int RELU>
__global__ void gk(const float* __restrict__ A, const float* __restrict__ B,
                   float* __restrict__ C, const float* __restrict__ bias,
                   int M, int N, int K, int lda, int ldb, int ldc, float alpha,
                   int zm, long long a1, long long a2, long long b1, long long b2,
                   long long c1, long long c2) {
    int z = blockIdx.z, z1 = z % zm, z2 = z / zm;
    A += z1*a1 + z2*a2; B += z1*b1 + z2*b2; C += z1*c1 + z2*c2;
    __shared__ float As[16][64], Bs[16][64];
    int tx = threadIdx.x & 15, ty = threadIdx.x >> 4;
    int m0 = blockIdx.y*64, n0 = blockIdx.x*64;
    float acc[4][4] = {};
    for (int k0 = 0; k0 < K; k0 += 16) {
        for (int i = threadIdx.x; i < 1024; i += 256) {
            int mm = i >> 4, kk = i & 15;
            As[kk][mm] = (m0+mm < M && k0+kk < K) ? A[(long long)(m0+mm)*lda + k0+kk] : 0.f;
            float bv = 0.f;
            if (n0+mm < N && k0+kk < K)
                bv = TB ? B[(long long)(n0+mm)*ldb + k0+kk] : B[(long long)(k0+kk)*ldb + n0+mm];
            Bs[kk][mm] = bv;
        }
        __syncthreads();
        #pragma unroll
        for (int kk = 0; kk < 16; kk++) {
            float av[4], bv[4];
            #pragma unroll
            for (int i = 0; i < 4; i++) { av[i] = As[kk][ty + i*16]; bv[i] = Bs[kk][tx + i*16]; }
            #pragma unroll
            for (int i = 0; i < 4; i++)
                #pragma unroll
                for (int j = 0; j < 4; j++) acc[i][j] += av[i]*bv[j];
        }
        __syncthreads();
    }
    #pragma unroll
    for (int i = 0; i < 4; i++)
        #pragma unroll
        for (int j = 0; j < 4; j++) {
            int m = m0 + ty + i*16, n = n0 + tx + j*16;
            if (m < M && n < N) {
                float v = alpha*acc[i][j];
                if (bias) v += bias[n];
                if (RELU) v = fmaxf(v, 0.f);
                C[(long long)m*ldc + n] = v;
            }
        }
}

// ---------- small kernels ----------
__global__ void k_buildh(const float* __restrict__ fc1o, const float* __restrict__ cls) {
    long long idx = blockIdx.x*256ll + threadIdx.x;
    if (idx >= 2ll*NSEQ*DM) return;
    int c = (int)(idx % DM); long long r = idx / DM; int b = (int)(r / NSEQ); int i = (int)(r % NSEQ);
    float v;
    if (i == 0) v = cls[c];
    else { int t = i-1; if (t >= NTOK) t -= NTOK; v = fc1o[((long long)b*NTOK + t)*DM + c]; }
    d_h[idx] = v;
}

__global__ void k_lnpad(const float* __restrict__ w, const float* __restrict__ bia) {
    int r = blockIdx.x; int b = r / NPAD, rr = r % NPAD;
    float* o = d_xln + (long long)r*DM;
    int t = threadIdx.x;
    if (rr < PADF) { o[t] = 0.f; o[t+256] = 0.f; return; }
    const float* in = d_h + ((long long)b*NSEQ + rr - PADF)*DM;
    __shared__ float red[256];
    float v0 = in[t], v1 = in[t+256];
    red[t] = v0+v1; __syncthreads();
    for (int s = 128; s > 0; s >>= 1) { if (t < s) red[t] += red[t+s]; __syncthreads(); }
    float mu = red[0]*(1.f/DM); __syncthreads();
    float e0 = v0-mu, e1 = v1-mu;
    red[t] = e0*e0+e1*e1; __syncthreads();
    for (int s = 128; s > 0; s >>= 1) { if (t < s) red[t] += red[t+s]; __syncthreads(); }
    float rstd = rsqrtf(red[0]*(1.f/DM) + 1e-5f);
    o[t]     = e0*rstd*w[t]     + bia[t];
    o[t+256] = e1*rstd*w[t+256] + bia[t+256];
}

__global__ void k_lm() {
    int z = blockIdx.y, j = blockIdx.x, dd = threadIdx.x;
    int b = z >> 3, hh = z & 7;
    const float* base = d_qkv + (long long)b*NPAD*QW + (long long)j*64*QW + hh*HD + dd;
    float sq = 0.f, sk = 0.f;
    for (int i = 0; i < 64; i++) { sq += base[(long long)i*QW]; sk += base[(long long)i*QW + DM]; }
    d_ql[(z*NLM+j)*HD+dd] = sq*(1.f/64.f);
    d_kl[(z*NLM+j)*HD+dd] = sk*(1.f/64.f);
}

__global__ void k_sm(float* __restrict__ p, int L) {
    p += (long long)blockIdx.x * L;
    int t = threadIdx.x;
    __shared__ float red[256];
    float m = -1e30f;
    for (int i = t; i < L; i += 256) m = fmaxf(m, p[i]);
    red[t] = m; __syncthreads();
    for (int s = 128; s > 0; s >>= 1) { if (t < s) red[t] = fmaxf(red[t], red[t+s]); __syncthreads(); }
    m = red[0]; __syncthreads();
    float sum = 0.f;
    for (int i = t; i < L; i += 256) sum += __expf(p[i]-m);
    red[t] = sum; __syncthreads();
    for (int s = 128; s > 0; s >>= 1) { if (t < s) red[t] += red[t+s]; __syncthreads(); }
    float inv = 1.f/red[0];
    for (int i = t; i < L; i += 256) p[i] = __expf(p[i]-m)*inv;
}

__global__ void k_init() { d_sc[0] = 0; d_sc[1] = 0; }

__global__ void k_rmax() {
    int mb = blockIdx.x >> 8, i = blockIdx.x & 255, t = threadIdx.x;
    __shared__ float red[256];
    red[t] = fabsf(d_a2[((long long)mb*256+i)*256 + t]); __syncthreads();
    for (int s = 128; s > 0; s >>= 1) { if (t < s) red[t] += red[t+s]; __syncthreads(); }
    if (t == 0) atomicMax(&d_sc[0], __float_as_int(red[0]));
}

__global__ void k_cmax() {
    int mb = blockIdx.x, j = threadIdx.x;
    float s = 0.f;
    for (int i = 0; i < 256; i++) s += fabsf(d_a2[((long long)mb*256+i)*256 + j]);
    atomicMax(&d_sc[1], __float_as_int(s));
}

__global__ void k_tz() {
    long long idx = blockIdx.x*256ll + threadIdx.x;
    if (idx >= (long long)BH*65536) return;
    int mb = (int)(idx >> 16); int r = (int)((idx >> 8) & 255); int c = (int)(idx & 255);
    float sc = __int_as_float(d_sc[0]) * __int_as_float(d_sc[1]);
    d_z[idx] = d_a2[(long long)mb*65536 + (long long)c*256 + r] / sc;
}

__global__ void k_ci(const float* __restrict__ in, float* __restrict__ o, float c) {
    long long idx = blockIdx.x*256ll + threadIdx.x;
    if (idx >= (long long)BH*65536) return;
    int r = (int)((idx >> 8) & 255); int cc = (int)(idx & 255);
    o[idx] = (r == cc ? c : 0.f) - in[idx];
}

__global__ void k_dw(const float* __restrict__ w) {
    int z = blockIdx.y; int b = z >> 3, hh = z & 7;
    int i = blockIdx.x*4 + threadIdx.y;
    int dd = threadIdx.x;
    const float* v = d_qkv + (long long)b*NPAD*QW + 2*DM + hh*HD + dd;
    float s = 0.f;
    #pragma unroll
    for (int tp = 0; tp < 33; tp++) {
        int ii = i + tp - 16;
        if (ii >= 0 && ii < NPAD) s += w[hh*33+tp] * v[(long long)ii*QW];
    }
    d_ao[((long long)b*NPAD + i)*DM + hh*HD + dd] += s;
}

__global__ void k_radd() {
    long long idx = blockIdx.x*256ll + threadIdx.x;
    if (idx >= 2ll*NSEQ*DM) return;
    int c = (int)(idx % DM); long long r = idx / DM; int b = (int)(r / NSEQ); int i = (int)(r % NSEQ);
    d_h[idx] += d_xln[((long long)b*NPAD + PADF + i)*DM + c];
}

__global__ void k_ppeg(const float* __restrict__ w7, const float* __restrict__ b7,
                       const float* __restrict__ w5, const float* __restrict__ b5,
                       const float* __restrict__ w3, const float* __restrict__ b3) {
    int p = blockIdx.x, b = blockIdx.y, c = threadIdx.x;
    int r = p / GR, ww = p % GR;
    const float* base = d_h + ((long long)b*NSEQ + 1)*DM + c;
    float acc = base[(long long)p*DM] + b7[c] + b5[c] + b3[c];
    for (int i = 0; i < 7; i++) {
        int rr = r + i - 3; if (rr < 0 || rr >= GR) continue;
        for (int j = 0; j < 7; j++) {
            int cc = ww + j - 3; if (cc < 0 || cc >= GR) continue;
            float x = base[(long long)(rr*GR+cc)*DM];
            acc += w7[c*49 + i*7 + j] * x;
            if (i >= 1 && i < 6 && j >= 1 && j < 6) acc += w5[c*25 + (i-1)*5 + (j-1)] * x;
            if (i >= 2 && i < 5 && j >= 2 && j < 5) acc += w3[c*9 + (i-2)*3 + (j-2)] * x;
        }
    }
    d_xln[((long long)b*NFEAT + p)*DM + c] = acc;
}

__global__ void k_ppcp() {
    long long idx = blockIdx.x*256ll + threadIdx.x;
    if (idx >= 2ll*NFEAT*DM) return;
    int c = (int)(idx % DM); long long r = idx / DM; int b = (int)(r / NFEAT); int p = (int)(r % NFEAT);
    d_h[((long long)b*NSEQ + 1 + p)*DM + c] = d_xln[idx];
}

__global__ void k_head(const float* __restrict__ nw, const float* __restrict__ nb,
                       const float* __restrict__ f2w, const float* __restrict__ f2b,
                       float* __restrict__ out) {
    int b = blockIdx.x, t = threadIdx.x;
    const float* x = d_h + (long long)b*NSEQ*DM;
    __shared__ float red[256];
    float v0 = x[t], v1 = x[t+256];
    red[t] = v0+v1; __syncthreads();
    for (int s = 128; s > 0; s >>= 1) { if (t < s) red[t] += red[t+s]; __syncthreads(); }
    float mu = red[0]*(1.f/DM); __syncthreads();
    float e0 = v0-mu, e1 = v1-mu;
    red[t] = e0*e0+e1*e1; __syncthreads();
    for (int s = 128; s > 0; s >>= 1) { if (t < s) red[t] += red[t+s]; __syncthreads(); }
    float rstd = rsqrtf(red[0]*(1.f/DM) + 1e-5f);
    __syncthreads();
    float n0 = e0*rstd*nw[t] + nb[t], n1 = e1*rstd*nw[t+256] + nb[t+256];
    for (int j = 0; j < 2; j++) {
        red[t] = n0*f2w[j*DM+t] + n1*f2w[j*DM+t+256]; __syncthreads();
        for (int s = 128; s > 0; s >>= 1) { if (t < s) red[t] += red[t+s]; __syncthreads(); }
        if (t == 0) out[b*2+j] = red[0] + f2b[j];
        __syncthreads();
    }
}

// ---------- host ----------
static inline void G(int TB, int RELU, const float* A, const float* B, float* C, const float* bias,
                     int M, int N, int K, int lda, int ldb, int ldc, float al, int Z, int zm,
                     long long a1, long long a2, long long b1, long long b2, long long c1, long long c2) {
    dim3 g((N+63)/64, (M+63)/64, Z);
    if (TB && RELU) gk<1,1><<<g,256>>>(A,B,C,bias,M,N,K,lda,ldb,ldc,al,zm,a1,a2,b1,b2,c1,c2);
    else if (TB)    gk<1,0><<<g,256>>>(A,B,C,bias,M,N,K,lda,ldb,ldc,al,zm,a1,a2,b1,b2,c1,c2);
    else            gk<0,0><<<g,256>>>(A,B,C,bias,M,N,K,lda,ldb,ldc,al,zm,a1,a2,b1,b2,c1,c2);
}

extern "C" void kernel_launch(void* const* d_in, const int* in_sizes, int n_in,
                              void* d_out, int out_size) {
    const float* x    = (const float*)d_in[0];
    const float* fc1w = (const float*)d_in[1];
    const float* fc1b = (const float*)d_in[2];
    const float* cls  = (const float*)d_in[3];
    const float* lnw  = (const float*)d_in[4];
    const float* lnb  = (const float*)d_in[5];
    const float* qkvw = (const float*)d_in[6];
    const float* qkvb = (const float*)d_in[7];
    const float* aow  = (const float*)d_in[8];
    const float* aob  = (const float*)d_in[9];
    const float* rcw  = (const float*)d_in[10];
    const float* w7 = (const float*)d_in[11]; const float* b7 = (const float*)d_in[12];
    const float* w5 = (const float*)d_in[13]; const float* b5 = (const float*)d_in[14];
    const float* w3 = (const float*)d_in[15]; const float* b3 = (const float*)d_in[16];
    const float* nw = (const float*)d_in[17]; const float* nb = (const float*)d_in[18];
    const float* f2w = (const float*)d_in[19]; const float* f2b = (const float*)d_in[20];
    float* out = (float*)d_out;

    float *h, *xln, *qkv, *sbuf, *ao, *ql, *kl, *a2, *z, *z2, *az, *tt, *uu, *t3, *w;
    cudaGetSymbolAddress((void**)&h, d_h);
    cudaGetSymbolAddress((void**)&xln, d_xln);
    cudaGetSymbolAddress((void**)&qkv, d_qkv);
    cudaGetSymbolAddress((void**)&sbuf, d_sbuf);
    cudaGetSymbolAddress((void**)&ao, d_ao);
    cudaGetSymbolAddress((void**)&ql, d_ql);
    cudaGetSymbolAddress((void**)&kl, d_kl);
    cudaGetSymbolAddress((void**)&a2, d_a2);
    cudaGetSymbolAddress((void**)&z, d_z);
    cudaGetSymbolAddress((void**)&z2, d_z2);
    cudaGetSymbolAddress((void**)&az, d_az);
    cudaGetSymbolAddress((void**)&tt, d_tt);
    cudaGetSymbolAddress((void**)&uu, d_uu);
    cudaGetSymbolAddress((void**)&t3, d_t3);
    cudaGetSymbolAddress((void**)&w, d_w);

    const long long SQ = (long long)NPAD*QW;   // qkv batch stride
    const long long SD = (long long)NPAD*DM;   // 16384x512 batch stride
    const long long SS3 = (long long)NLM*NPAD; // score mat stride (attn3 per z)
    const long long SS1 = (long long)NPAD*NLM;
    const int EWB = (BH*65536 + 255)/256;

    // fc1 + relu -> sbuf (32000,512); then assemble h
    G(1,1, x, fc1w, sbuf, fc1b, 2*NTOK, DM, 1024, 1024, 1024, DM, 1.f, 1,1, 0,0,0,0,0,0);
    k_buildh<<<(int)((2ll*NSEQ*DM+255)/256),256>>>(sbuf, cls);

    for (int l = 0; l < 2; l++) {
        k_lnpad<<<2*NPAD,256>>>(lnw + l*DM, lnb + l*DM);
        G(1,0, xln, qkvw + (long long)l*QW*DM, qkv, qkvb + l*QW,
          NPAD, QW, DM, DM, DM, QW, 1.f, 2,2, SD,0, 0,0, SQ,0);
        k_lm<<<dim3(256,16),64>>>();
        // attn2 = softmax(0.125 * ql @ kl^T)
        G(1,0, ql, kl, a2, 0, NLM, NLM, HD, HD, HD, NLM, 0.125f, BH,BH,
          NLM*HD,0, NLM*HD,0, NLM*NLM,0);
        k_sm<<<BH*NLM,256>>>(a2, NLM);
        // pinv(attn2) -> z
        k_init<<<1,1>>>();
        k_rmax<<<BH*NLM,256>>>();
        k_cmax<<<BH,256>>>();
        k_tz<<<EWB,256>>>();
        float* zc = z; float* zn = z2;
        for (int it = 0; it < 6; it++) {
            G(0,0, a2, zc, az, 0, NLM,NLM,NLM, NLM,NLM,NLM, 1.f, BH,BH, 65536,0,65536,0,65536,0);
            k_ci<<<EWB,256>>>(az, tt, 7.f);
            G(0,0, az, tt, uu, 0, NLM,NLM,NLM, NLM,NLM,NLM, 1.f, BH,BH, 65536,0,65536,0,65536,0);
            k_ci<<<EWB,256>>>(uu, tt, 15.f);
            G(0,0, az, tt, uu, 0, NLM,NLM,NLM, NLM,NLM,NLM, 1.f, BH,BH, 65536,0,65536,0,65536,0);
            k_ci<<<EWB,256>>>(uu, tt, 13.f);
            G(0,0, zc, tt, zn, 0, NLM,NLM,NLM, NLM,NLM,NLM, 0.25f, BH,BH, 65536,0,65536,0,65536,0);
            float* sw = zc; zc = zn; zn = sw;
        }
        // S3 = softmax(0.125 * ql @ k^T)   (16,256,16384) in sbuf
        G(1,0, ql, qkv + DM, sbuf, 0, NLM, NPAD, HD, HD, QW, NPAD, 0.125f, BH,8,
          NLM*HD, 8ll*NLM*HD, HD, SQ, SS3, 8ll*SS3);
        k_sm<<<BH*NLM,256>>>(sbuf, NPAD);
        // t3 = S3 @ v  (16,256,64)
        G(0,0, sbuf, qkv + 2*DM, t3, 0, NLM, HD, NPAD, NPAD, QW, HD, 1.f, BH,8,
          SS3, 8ll*SS3, HD, SQ, NLM*HD, 8ll*NLM*HD);
        // w = pinv @ t3
        G(0,0, zc, t3, w, 0, NLM, HD, NLM, NLM, HD, HD, 1.f, BH,BH,
          65536,0, NLM*HD,0, NLM*HD,0);
        // S1 = softmax(0.125 * q @ kl^T)  (16,16384,256) in sbuf
        G(1,0, qkv, kl, sbuf, 0, NPAD, NLM, HD, QW, HD, NLM, 0.125f, BH,8,
          HD, SQ, NLM*HD, 8ll*NLM*HD, SS1, 8ll*SS1);
        k_sm<<<BH*NPAD,256>>>(sbuf, NLM);
        // ao = S1 @ w  (writes into (b,i,hh*64+dd))
        G(0,0, sbuf, w, ao, 0, NPAD, HD, NLM, NLM, HD, DM, 1.f, BH,8,
          SS1, 8ll*SS1, NLM*HD, 8ll*NLM*HD, HD, SD);
        // depthwise residual conv over v
        k_dw<<<dim3(NPAD/4,BH),dim3(64,4)>>>(rcw + l*264);
        // out projection + residual
        G(1,0, ao, aow + (long long)l*DM*DM, xln, aob + l*DM,
          NPAD, DM, DM, DM, DM, DM, 1.f, 2,2, SD,0, 0,0, SD,0);
        k_radd<<<(int)((2ll*NSEQ*DM+255)/256),256>>>();
        if (l == 0) {
            k_ppeg<<<dim3(NFEAT,2),512>>>(w7,b7,w5,b5,w3,b3);
            k_ppcp<<<(int)((2ll*NFEAT*DM+255)/256),256>>>();
        }
    }
    k_head<<<2,256>>>(nw, nb, f2w, f2b, out);
}

// round 5
// speedup vs baseline: 1.8188x; 1.8188x over previous
#include <cuda_runtime.h>
#include <math.h>

#define NSEQ 16130
#define NPAD 16384
#define PADF 254
#define NLM 256
#define DM 512
#define QW 1536
#define HD 64
#define BH 16
#define NTOK 16000
#define NFEAT 16129
#define GR 127
#define NSPL 32
#define KSPL 512

// ---------- static scratch ----------
__device__ float d_h[2ll*NSEQ*DM];
__device__ float d_xln[2ll*NPAD*DM];
__device__ float d_qkv[2ll*NPAD*QW];
__device__ float d_sbuf[(long long)BH*NPAD*NLM];
__device__ float d_ao[2ll*NPAD*DM];
__device__ float d_q[(long long)BH*NPAD*HD];
__device__ float d_k[(long long)BH*NPAD*HD];
__device__ float d_v[(long long)BH*NPAD*HD];
__device__ float d_part[(long long)NSPL*BH*NLM*HD];
__device__ float d_ql[BH*NLM*HD], d_kl[BH*NLM*HD];
__device__ float d_a2[BH*NLM*NLM], d_z[BH*NLM*NLM], d_z2[BH*NLM*NLM];
__device__ float d_az[BH*NLM*NLM], d_tt[BH*NLM*NLM], d_uu[BH*NLM*NLM];
__device__ float d_t3[BH*NLM*HD], d_w[BH*NLM*HD];
__device__ int d_sc[2];

// ---------- 64x64 tiled SGEMM (small shapes: pinv chain, attn2, z@t3) ----------
template<int TB>
__global__ void gk(const float* __restrict__ A, const float* __restrict__ B,
                   float* __restrict__ C, const float* __restrict__ bias,
                   int M, int N, int K, int lda, int ldb, int ldc, float alpha,
                   int zm, long long a1, long long a2, long long b1, long long b2,
                   long long c1, long long c2) {
    int z = blockIdx.z, z1 = z % zm, z2 = z / zm;
    A += z1*a1 + z2*a2; B += z1*b1 + z2*b2; C += z1*c1 + z2*c2;
    __shared__ float As[16][64], Bs[16][64];
    int tx = threadIdx.x & 15, ty = threadIdx.x >> 4;
    int m0 = blockIdx.y*64, n0 = blockIdx.x*64;
    float acc[4][4] = {};
    for (int k0 = 0; k0 < K; k0 += 16) {
        for (int i = threadIdx.x; i < 1024; i += 256) {
            int mm = i >> 4, kk = i & 15;
            As[kk][mm] = (m0+mm < M && k0+kk < K) ? A[(long long)(m0+mm)*lda + k0+kk] : 0.f;
            float bv = 0.f;
            if (n0+mm < N && k0+kk < K)
                bv = TB ? B[(long long)(n0+mm)*ldb + k0+kk] : B[(long long)(k0+kk)*ldb + n0+mm];
            Bs[kk][mm] = bv;
        }
        __syncthreads();
        #pragma unroll
        for (int kk = 0; kk < 16; kk++) {
            float av[4], bv[4];
            #pragma unroll
            for (int i = 0; i < 4; i++) { av[i] = As[kk][ty + i*16]; bv[i] = Bs[kk][tx + i*16]; }
            #pragma unroll
            for (int i = 0; i < 4; i++)
                #pragma unroll
                for (int j = 0; j < 4; j++) acc[i][j] += av[i]*bv[j];
        }
        __syncthreads();
    }
    #pragma unroll
    for (int i = 0; i < 4; i++)
        #pragma unroll
        for (int j = 0; j < 4; j++) {
            int m = m0 + ty + i*16, n = n0 + tx + j*16;
            if (m < M && n < N) {
                float v = alpha*acc[i][j];
                if (bias) v += bias[n];
                C[(long long)m*ldc + n] = v;
            }
        }
}

// ---------- 128x128x16 SGEMM, 8x8 microtile, vectorized smem reads ----------
template<int TB, int RELU>
__global__ void __launch_bounds__(256) gk128(
    const float* __restrict__ A, const float* __restrict__ B,
    float* __restrict__ C, const float* __restrict__ bias,
    int M, int N, int K, int lda, int ldb, int ldc, float alpha,
    int zm, long long sa1, long long sa2, long long sb1, long long sb2,
    long long sc1, long long sc2)
{
    int z = blockIdx.z, z1 = z % zm, z2 = z / zm;
    A += (long long)z1*sa1 + (long long)z2*sa2;
    B += (long long)z1*sb1 + (long long)z2*sb2;
    C += (long long)z1*sc1 + (long long)z2*sc2;
    __shared__ float As[16][132], Bs[16][132];
    int tid = threadIdx.x;
    int tx = tid & 15, ty = tid >> 4;
    int m0 = blockIdx.y*128, n0 = blockIdx.x*128;
    float acc[8][8] = {};
    for (int k0 = 0; k0 < K; k0 += 16) {
        #pragma unroll
        for (int j = 0; j < 8; j++) {
            int i = tid + j*256;
            int kk = i & 15, mm = i >> 4;
            As[kk][mm] = (m0+mm < M && k0+kk < K) ? A[(long long)(m0+mm)*lda + k0+kk] : 0.f;
        }
        if (TB) {
            #pragma unroll
            for (int j = 0; j < 8; j++) {
                int i = tid + j*256;
                int kk = i & 15, nn = i >> 4;
                Bs[kk][nn] = (n0+nn < N && k0+kk < K) ? B[(long long)(n0+nn)*ldb + k0+kk] : 0.f;
            }
        } else {
            #pragma unroll
            for (int j = 0; j < 8; j++) {
                int i = tid + j*256;
                int kk = i >> 7, nn = i & 127;
                Bs[kk][nn] = (n0+nn < N && k0+kk < K) ? B[(long long)(k0+kk)*ldb + n0+nn] : 0.f;
            }
        }
        __syncthreads();
        #pragma unroll
        for (int kk = 0; kk < 16; kk++) {
            float4 va0 = *(const float4*)&As[kk][ty*4];
            float4 va1 = *(const float4*)&As[kk][ty*4+64];
            float4 vb0 = *(const float4*)&Bs[kk][tx*4];
            float4 vb1 = *(const float4*)&Bs[kk][tx*4+64];
            float av[8] = {va0.x,va0.y,va0.z,va0.w,va1.x,va1.y,va1.z,va1.w};
            float bv[8] = {vb0.x,vb0.y,vb0.z,vb0.w,vb1.x,vb1.y,vb1.z,vb1.w};
            #pragma unroll
            for (int i = 0; i < 8; i++)
                #pragma unroll
                for (int j = 0; j < 8; j++) acc[i][j] += av[i]*bv[j];
        }
        __syncthreads();
    }
    #pragma unroll
    for (int i = 0; i < 8; i++) {
        int m = m0 + ((i < 4) ? ty*4+i : 64+ty*4+i-4);
        if (m >= M) continue;
        #pragma unroll
        for (int j = 0; j < 8; j++) {
            int n = n0 + ((j < 4) ? tx*4+j : 64+tx*4+j-4);
            if (n >= N) continue;
            float v = alpha*acc[i][j];
            if (bias) v += bias[n];
            if (RELU) v = fmaxf(v, 0.f);
            C[(long long)m*ldc + n] = v;
        }
    }
}

// ---------- small kernels ----------
__global__ void k_buildh(const float* __restrict__ fc1o, const float* __restrict__ cls) {
    long long idx = blockIdx.x*256ll + threadIdx.x;
    if (idx >= 2ll*NSEQ*DM) return;
    int c = (int)(idx % DM); long long r = idx / DM; int b = (int)(r / NSEQ); int i = (int)(r % NSEQ);
    float v;
    if (i == 0) v = cls[c];
    else { int t = i-1; if (t >= NTOK) t -= NTOK; v = fc1o[((long long)b*NTOK + t)*DM + c]; }
    d_h[idx] = v;
}

__global__ void k_lnpad(const float* __restrict__ w, const float* __restrict__ bia) {
    int r = blockIdx.x; int b = r / NPAD, rr = r % NPAD;
    float* o = d_xln + (long long)r*DM;
    int t = threadIdx.x;
    if (rr < PADF) { o[t] = 0.f; o[t+256] = 0.f; return; }
    const float* in = d_h + ((long long)b*NSEQ + rr - PADF)*DM;
    __shared__ float red[256];
    float v0 = in[t], v1 = in[t+256];
    red[t] = v0+v1; __syncthreads();
    for (int s = 128; s > 0; s >>= 1) { if (t < s) red[t] += red[t+s]; __syncthreads(); }
    float mu = red[0]*(1.f/DM); __syncthreads();
    float e0 = v0-mu, e1 = v1-mu;
    red[t] = e0*e0+e1*e1; __syncthreads();
    for (int s = 128; s > 0; s >>= 1) { if (t < s) red[t] += red[t+s]; __syncthreads(); }
    float rstd = rsqrtf(red[0]*(1.f/DM) + 1e-5f);
    o[t]     = e0*rstd*w[t]     + bia[t];
    o[t+256] = e1*rstd*w[t+256] + bia[t+256];
}

// split qkv [b][n][1536] -> q/k/v [(b*8+h)][n][64]
__global__ void k_splitqkv() {
    long long idx = blockIdx.x*256ll + threadIdx.x;
    if (idx >= 2ll*NPAD*DM) return;
    int c = (int)(idx % DM);
    long long bn = idx / DM;
    int hh = c >> 6, dd = c & 63;
    int b = (int)(bn / NPAD), n = (int)(bn % NPAD);
    long long src = bn*QW + c;
    long long dst = (((long long)(b*8+hh)*NPAD) + n)*HD + dd;
    d_q[dst] = d_qkv[src];
    d_k[dst] = d_qkv[src + DM];
    d_v[dst] = d_qkv[src + 2*DM];
}

__global__ void k_lm() {
    int z = blockIdx.y, j = blockIdx.x, dd = threadIdx.x;
    const float* q = d_q + ((long long)z*NPAD + j*64)*HD + dd;
    const float* k = d_k + ((long long)z*NPAD + j*64)*HD + dd;
    float sq = 0.f, sk = 0.f;
    #pragma unroll 8
    for (int i = 0; i < 64; i++) { sq += q[i*HD]; sk += k[i*HD]; }
    d_ql[(z*NLM+j)*HD+dd] = sq*(1.f/64.f);
    d_kl[(z*NLM+j)*HD+dd] = sk*(1.f/64.f);
}

__global__ void k_sm(float* __restrict__ p, int L) {
    p += (long long)blockIdx.x * L;
    int t = threadIdx.x;
    __shared__ float red[256];
    float m = -1e30f;
    for (int i = t; i < L; i += 256) m = fmaxf(m, p[i]);
    red[t] = m; __syncthreads();
    for (int s = 128; s > 0; s >>= 1) { if (t < s) red[t] = fmaxf(red[t], red[t+s]); __syncthreads(); }
    m = red[0]; __syncthreads();
    float sum = 0.f;
    for (int i = t; i < L; i += 256) sum += __expf(p[i]-m);
    red[t] = sum; __syncthreads();
    for (int s = 128; s > 0; s >>= 1) { if (t < s) red[t] += red[t+s]; __syncthreads(); }
    float inv = 1.f/red[0];
    for (int i = t; i < L; i += 256) p[i] = __expf(p[i]-m)*inv;
}

__global__ void k_init() { d_sc[0] = 0; d_sc[1] = 0; }

__global__ void k_rmax() {
    int mb = blockIdx.x >> 8, i = blockIdx.x & 255, t = threadIdx.x;
    __shared__ float red[256];
    red[t] = fabsf(d_a2[((long long)mb*256+i)*256 + t]); __syncthreads();
    for (int s = 128; s > 0; s >>= 1) { if (t < s) red[t] += red[t+s]; __syncthreads(); }
    if (t == 0) atomicMax(&d_sc[0], __float_as_int(red[0]));
}

__global__ void k_cmax() {
    int mb = blockIdx.x, j = threadIdx.x;
    float s = 0.f;
    for (int i = 0; i < 256; i++) s += fabsf(d_a2[((long long)mb*256+i)*256 + j]);
    atomicMax(&d_sc[1], __float_as_int(s));
}

__global__ void k_tz() {
    long long idx = blockIdx.x*256ll + threadIdx.x;
    if (idx >= (long long)BH*65536) return;
    int mb = (int)(idx >> 16); int r = (int)((idx >> 8) & 255); int c = (int)(idx & 255);
    float sc = __int_as_float(d_sc[0]) * __int_as_float(d_sc[1]);
    d_z[idx] = d_a2[(long long)mb*65536 + (long long)c*256 + r] / sc;
}

__global__ void k_ci(const float* __restrict__ in, float* __restrict__ o, float c) {
    long long idx = blockIdx.x*256ll + threadIdx.x;
    if (idx >= (long long)BH*65536) return;
    int r = (int)((idx >> 8) & 255); int cc = (int)(idx & 255);
    o[idx] = (r == cc ? c : 0.f) - in[idx];
}

__global__ void k_red() {
    int idx = blockIdx.x*256 + threadIdx.x;
    if (idx >= BH*NLM*HD) return;
    float s = 0.f;
    #pragma unroll
    for (int p = 0; p < NSPL; p++) s += d_part[(long long)p*BH*NLM*HD + idx];
    d_t3[idx] = s;
}

__global__ void k_dw(const float* __restrict__ w) {
    int z = blockIdx.y; int b = z >> 3, hh = z & 7;
    int i = blockIdx.x*4 + threadIdx.y;
    int dd = threadIdx.x;
    const float* v = d_v + (long long)z*NPAD*HD + dd;
    float s = 0.f;
    #pragma unroll
    for (int tp = 0; tp < 33; tp++) {
        int ii = i + tp - 16;
        if (ii >= 0 && ii < NPAD) s += w[hh*33+tp] * v[(long long)ii*HD];
    }
    d_ao[((long long)b*NPAD + i)*DM + hh*HD + dd] += s;
}

__global__ void k_radd() {
    long long idx = blockIdx.x*256ll + threadIdx.x;
    if (idx >= 2ll*NSEQ*DM) return;
    int c = (int)(idx % DM); long long r = idx / DM; int b = (int)(r / NSEQ); int i = (int)(r % NSEQ);
    d_h[idx] += d_xln[((long long)b*NPAD + PADF + i)*DM + c];
}

__global__ void k_ppeg(const float* __restrict__ w7, const float* __restrict__ b7,
                       const float* __restrict__ w5, const float* __restrict__ b5,
                       const float* __restrict__ w3, const float* __restrict__ b3) {
    int p = blockIdx.x, b = blockIdx.y, c = threadIdx.x;
    int r = p / GR, ww = p % GR;
    const float* base = d_h + ((long long)b*NSEQ + 1)*DM + c;
    float acc = base[(long long)p*DM] + b7[c] + b5[c] + b3[c];
    for (int i = 0; i < 7; i++) {
        int rr = r + i - 3; if (rr < 0 || rr >= GR) continue;
        for (int j = 0; j < 7; j++) {
            int cc = ww + j - 3; if (cc < 0 || cc >= GR) continue;
            float x = base[(long long)(rr*GR+cc)*DM];
            acc += w7[c*49 + i*7 + j] * x;
            if (i >= 1 && i < 6 && j >= 1 && j < 6) acc += w5[c*25 + (i-1)*5 + (j-1)] * x;
            if (i >= 2 && i < 5 && j >= 2 && j < 5) acc += w3[c*9 + (i-2)*3 + (j-2)] * x;
        }
    }
    d_xln[((long long)b*NFEAT + p)*DM + c] = acc;
}

__global__ void k_ppcp() {
    long long idx = blockIdx.x*256ll + threadIdx.x;
    if (idx >= 2ll*NFEAT*DM) return;
    int c = (int)(idx % DM); long long r = idx / DM; int b = (int)(r / NFEAT); int p = (int)(r % NFEAT);
    d_h[((long long)b*NSEQ + 1 + p)*DM + c] = d_xln[idx];
}

__global__ void k_head(const float* __restrict__ nw, const float* __restrict__ nb,
                       const float* __restrict__ f2w, const float* __restrict__ f2b,
                       float* __restrict__ out) {
    int b = blockIdx.x, t = threadIdx.x;
    const float* x = d_h + (long long)b*NSEQ*DM;
    __shared__ float red[256];
    float v0 = x[t], v1 = x[t+256];
    red[t] = v0+v1; __syncthreads();
    for (int s = 128; s > 0; s >>= 1) { if (t < s) red[t] += red[t+s]; __syncthreads(); }
    float mu = red[0]*(1.f/DM); __syncthreads();
    float e0 = v0-mu, e1 = v1-mu;
    red[t] = e0*e0+e1*e1; __syncthreads();
    for (int s = 128; s > 0; s >>= 1) { if (t < s) red[t] += red[t+s]; __syncthreads(); }
    float rstd = rsqrtf(red[0]*(1.f/DM) + 1e-5f);
    __syncthreads();
    float n0 = e0*rstd*nw[t] + nb[t], n1 = e1*rstd*nw[t+256] + nb[t+256];
    for (int j = 0; j < 2; j++) {
        red[t] = n0*f2w[j*DM+t] + n1*f2w[j*DM+t+256]; __syncthreads();
        for (int s = 128; s > 0; s >>= 1) { if (t < s) red[t] += red[t+s]; __syncthreads(); }
        if (t == 0) out[b*2+j] = red[0] + f2b[j];
        __syncthreads();
    }
}

// ---------- host wrappers ----------
static inline void G64(int TB, const float* A, const float* B, float* C, const float* bias,
                     int M, int N, int K, int lda, int ldb, int ldc, float al, int Z, int zm,
                     long long a1, long long a2, long long b1, long long b2, long long c1, long long c2) {
    dim3 g((N+63)/64, (M+63)/64, Z);
    if (TB) gk<1><<<g,256>>>(A,B,C,bias,M,N,K,lda,ldb,ldc,al,zm,a1,a2,b1,b2,c1,c2);
    else    gk<0><<<g,256>>>(A,B,C,bias,M,N,K,lda,ldb,ldc,al,zm,a1,a2,b1,b2,c1,c2);
}
static inline void G128(int TB, int RELU, const float* A, const float* B, float* C, const float* bias,
                     int M, int N, int K, int lda, int ldb, int ldc, float al, int Z, int zm,
                     long long a1, long long a2, long long b1, long long b2, long long c1, long long c2) {
    dim3 g((N+127)/128, (M+127)/128, Z);
    if (TB && RELU) gk128<1,1><<<g,256>>>(A,B,C,bias,M,N,K,lda,ldb,ldc,al,zm,a1,a2,b1,b2,c1,c2);
    else if (TB)    gk128<1,0><<<g,256>>>(A,B,C,bias,M,N,K,lda,ldb,ldc,al,zm,a1,a2,b1,b2,c1,c2);
    else            gk128<0,0><<<g,256>>>(A,B,C,bias,M,N,K,lda,ldb,ldc,al,zm,a1,a2,b1,b2,c1,c2);
}

extern "C" void kernel_launch(void* const* d_in, const int* in_sizes, int n_in,
                              void* d_out, int out_size) {
    const float* x    = (const float*)d_in[0];
    const float* fc1w = (const float*)d_in[1];
    const float* fc1b = (const float*)d_in[2];
    const float* cls  = (const float*)d_in[3];
    const float* lnw  = (const float*)d_in[4];
    const float* lnb  = (const float*)d_in[5];
    const float* qkvw = (const float*)d_in[6];
    const float* qkvb = (const float*)d_in[7];
    const float* aow  = (const float*)d_in[8];
    const float* aob  = (const float*)d_in[9];
    const float* rcw  = (const float*)d_in[10];
    const float* w7 = (const float*)d_in[11]; const float* b7 = (const float*)d_in[12];
    const float* w5 = (const float*)d_in[13]; const float* b5 = (const float*)d_in[14];
    const float* w3 = (const float*)d_in[15]; const float* b3 = (const float*)d_in[16];
    const float* nw = (const float*)d_in[17]; const float* nb = (const float*)d_in[18];
    const float* f2w = (const float*)d_in[19]; const float* f2b = (const float*)d_in[20];
    float* out = (float*)d_out;

    float *xln, *qkv, *sbuf, *ao, *q, *k, *v, *part;
    float *ql, *kl, *a2, *z, *z2, *az, *tt, *uu, *t3, *w;
    cudaGetSymbolAddress((void**)&xln, d_xln);
    cudaGetSymbolAddress((void**)&qkv, d_qkv);
    cudaGetSymbolAddress((void**)&sbuf, d_sbuf);
    cudaGetSymbolAddress((void**)&ao, d_ao);
    cudaGetSymbolAddress((void**)&q, d_q);
    cudaGetSymbolAddress((void**)&k, d_k);
    cudaGetSymbolAddress((void**)&v, d_v);
    cudaGetSymbolAddress((void**)&part, d_part);
    cudaGetSymbolAddress((void**)&ql, d_ql);
    cudaGetSymbolAddress((void**)&kl, d_kl);
    cudaGetSymbolAddress((void**)&a2, d_a2);
    cudaGetSymbolAddress((void**)&z, d_z);
    cudaGetSymbolAddress((void**)&z2, d_z2);
    cudaGetSymbolAddress((void**)&az, d_az);
    cudaGetSymbolAddress((void**)&tt, d_tt);
    cudaGetSymbolAddress((void**)&uu, d_uu);
    cudaGetSymbolAddress((void**)&t3, d_t3);
    cudaGetSymbolAddress((void**)&w, d_w);

    const long long SQ  = (long long)NPAD*QW;
    const long long SD  = (long long)NPAD*DM;
    const long long SH  = (long long)NPAD*HD;   // per-z q/k/v stride
    const long long SS3 = (long long)NLM*NPAD;  // per-z S3 stride
    const long long SS1 = (long long)NPAD*NLM;  // per-z S1 stride
    const int EWB = (BH*65536 + 255)/256;

    // fc1 + relu -> sbuf (32000,512); then assemble token stream h
    G128(1,1, x, fc1w, sbuf, fc1b, 2*NTOK, DM, 1024, 1024, 1024, DM, 1.f, 1,1, 0,0,0,0,0,0);
    k_buildh<<<(int)((2ll*NSEQ*DM+255)/256),256>>>(sbuf, cls);

    for (int l = 0; l < 2; l++) {
        k_lnpad<<<2*NPAD,256>>>(lnw + l*DM, lnb + l*DM);
        G128(1,0, xln, qkvw + (long long)l*QW*DM, qkv, qkvb + l*QW,
             NPAD, QW, DM, DM, DM, QW, 1.f, 2,2, SD,0, 0,0, SQ,0);
        k_splitqkv<<<(int)((2ll*NPAD*DM+255)/256),256>>>();
        k_lm<<<dim3(256,16),64>>>();
        // attn2 = softmax(0.125 * ql @ kl^T)
        G64(1, ql, kl, a2, 0, NLM, NLM, HD, HD, HD, NLM, 0.125f, BH,BH,
            NLM*HD,0, NLM*HD,0, NLM*NLM,0);
        k_sm<<<BH*NLM,256>>>(a2, NLM);
        // pinv(attn2) -> zc
        k_init<<<1,1>>>();
        k_rmax<<<BH*NLM,256>>>();
        k_cmax<<<BH,256>>>();
        k_tz<<<EWB,256>>>();
        float* zc = z; float* zn = z2;
        for (int it = 0; it < 6; it++) {
            G64(0, a2, zc, az, 0, NLM,NLM,NLM, NLM,NLM,NLM, 1.f, BH,BH, 65536,0,65536,0,65536,0);
            k_ci<<<EWB,256>>>(az, tt, 7.f);
            G64(0, az, tt, uu, 0, NLM,NLM,NLM, NLM,NLM,NLM, 1.f, BH,BH, 65536,0,65536,0,65536,0);
            k_ci<<<EWB,256>>>(uu, tt, 15.f);
            G64(0, az, tt, uu, 0, NLM,NLM,NLM, NLM,NLM,NLM, 1.f, BH,BH, 65536,0,65536,0,65536,0);
            k_ci<<<EWB,256>>>(uu, tt, 13.f);
            G64(0, zc, tt, zn, 0, NLM,NLM,NLM, NLM,NLM,NLM, 0.25f, BH,BH, 65536,0,65536,0,65536,0);
            float* sw = zc; zc = zn; zn = sw;
        }
        // S3 = softmax(0.125 * ql @ k^T)   [z][256][16384]
        G128(1,0, ql, k, sbuf, 0, NLM, NPAD, HD, HD, HD, NPAD, 0.125f, BH,BH,
             NLM*HD,0, SH,0, SS3,0);
        k_sm<<<BH*NLM,256>>>(sbuf, NPAD);
        // t3 = S3 @ v  split-K over 32 chunks of 512
        G128(0,0, sbuf, v, part, 0, NLM, HD, KSPL, NPAD, HD, HD, 1.f, BH*NSPL, BH,
             SS3, 512, SH, (long long)KSPL*HD, (long long)NLM*HD, (long long)BH*NLM*HD);
        k_red<<<(BH*NLM*HD+255)/256,256>>>();
        // w = pinv @ t3
        G64(0, zc, t3, w, 0, NLM, HD, NLM, NLM, HD, HD, 1.f, BH,BH,
            65536,0, NLM*HD,0, NLM*HD,0);
        // S1 = softmax(0.125 * q @ kl^T)  [z][16384][256]
        G128(1,0, q, kl, sbuf, 0, NPAD, NLM, HD, HD, HD, NLM, 0.125f, BH,BH,
             SH,0, NLM*HD,0, SS1,0);
        k_sm<<<BH*NPAD,256>>>(sbuf, NLM);
        // ao = S1 @ w  -> [b][n][h*64+d]
        G128(0,0, sbuf, w, ao, 0, NPAD, HD, NLM, NLM, HD, DM, 1.f, BH,8,
             SS1, 8ll*SS1, NLM*HD, 8ll*NLM*HD, HD, SD);
        // depthwise residual conv over v
        k_dw<<<dim3(NPAD/4,BH),dim3(64,4)>>>(rcw + l*264);
        // out projection + residual
        G128(1,0, ao, aow + (long long)l*DM*DM, xln, aob + l*DM,
             NPAD, DM, DM, DM, DM, DM, 1.f, 2,2, SD,0, 0,0, SD,0);
        k_radd<<<(int)((2ll*NSEQ*DM+255)/256),256>>>();
        if (l == 0) {
            k_ppeg<<<dim3(NFEAT,2),512>>>(w7,b7,w5,b5,w3,b3);
            k_ppcp<<<(int)((2ll*NFEAT*DM+255)/256),256>>>();
        }
    }
    k_head<<<2,256>>>(nw, nb, f2w, f2b, out);
}

// round 7
// speedup vs baseline: 2.0675x; 1.1367x over previous
#include <cuda_runtime.h>
#include <math.h>
#include <stdint.h>

#define NSEQ 16130
#define NPAD 16384
#define PADF 254
#define NLM 256
#define DM 512
#define QW 1536
#define HD 64
#define BH 16
#define NTOK 16000
#define NFEAT 16129
#define GR 127
#define NSPL 32
#define KSPL 512

// ---------- static scratch ----------
__device__ float d_h[2ll*NSEQ*DM];
__device__ float d_xln[2ll*NPAD*DM];
__device__ float d_qkv[2ll*NPAD*QW];
__device__ float d_sbuf[(long long)BH*NPAD*NLM];
__device__ float d_ao[2ll*NPAD*DM];
__device__ float d_q[(long long)BH*NPAD*HD];
__device__ float d_k[(long long)BH*NPAD*HD];
__device__ float d_v[(long long)BH*NPAD*HD];
__device__ float d_part[(long long)NSPL*BH*NLM*HD];
__device__ float d_ql[BH*NLM*HD], d_kl[BH*NLM*HD];
__device__ float d_a2[BH*NLM*NLM], d_z[BH*NLM*NLM], d_z2[BH*NLM*NLM];
__device__ float d_az[BH*NLM*NLM], d_tt[BH*NLM*NLM], d_uu[BH*NLM*NLM];
__device__ float d_t3[BH*NLM*HD], d_w[BH*NLM*HD];
__device__ int d_sc[2];

__device__ __forceinline__ uint32_t f2tf(float f) {
    uint32_t u;
    asm("cvt.rna.tf32.f32 %0, %1;" : "=r"(u) : "f"(f));
    return u;
}

// ---------- TF32 tensor-core GEMM ----------
// C = alpha * A @ op(B) (+bias) (+relu).  TB: B is [N][K] (row-major N) -> B^T.
// DB: B' = cd*I - B applied at load (pinv fusion; TB=0 only).
// Requires M%128==0, N%BN==0, K%16==0.
template<int TB, int RELU, int BN, int DB>
__global__ void __launch_bounds__(256) tk(
    const float* __restrict__ A, const float* __restrict__ B,
    float* __restrict__ C, const float* __restrict__ bias,
    int M, int N, int K, int lda, int ldb, int ldc, float alpha, float cd,
    int zm, long long sa1, long long sa2, long long sb1, long long sb2,
    long long sc1, long long sc2)
{
    int z = blockIdx.z, z1 = z % zm, z2 = z / zm;
    A += (long long)z1*sa1 + (long long)z2*sa2;
    B += (long long)z1*sb1 + (long long)z2*sb2;
    C += (long long)z1*sc1 + (long long)z2*sc2;

    __shared__ uint32_t As[16][136];
    __shared__ uint32_t Bs[16][BN+8];

    int tid = threadIdx.x, lane = tid & 31, warp = tid >> 5;
    int wm = warp & 3, wn = warp >> 2;          // 4x2 warp grid
    constexpr int WN = BN/2, NT = WN/8;
    int m0 = blockIdx.y*128, n0 = blockIdx.x*BN;

    float acc[2][NT][4];
    #pragma unroll
    for (int a = 0; a < 2; a++)
        #pragma unroll
        for (int b = 0; b < NT; b++)
            #pragma unroll
            for (int cc = 0; cc < 4; cc++) acc[a][b][cc] = 0.f;

    for (int k0 = 0; k0 < K; k0 += 16) {
        #pragma unroll
        for (int j = 0; j < 8; j++) {
            int idx = tid + j*256;
            int mm = idx >> 4, kk = idx & 15;
            As[kk][mm] = f2tf(A[(long long)(m0+mm)*lda + k0+kk]);
        }
        if (TB) {
            #pragma unroll
            for (int j = 0; j < BN/16; j++) {
                int idx = tid + j*256;
                int nn = idx >> 4, kk = idx & 15;
                Bs[kk][nn] = f2tf(B[(long long)(n0+nn)*ldb + k0+kk]);
            }
        } else {
            #pragma unroll
            for (int j = 0; j < BN/16; j++) {
                int idx = tid + j*256;
                int kk = idx / BN, nn = idx % BN;
                float v = B[(long long)(k0+kk)*ldb + n0+nn];
                if (DB) v = ((k0+kk) == (n0+nn) ? cd : 0.f) - v;
                Bs[kk][nn] = f2tf(v);
            }
        }
        __syncthreads();
        int r = lane >> 2, c = lane & 3;
        #pragma unroll
        for (int ks = 0; ks < 2; ks++) {
            int kb = ks*8;
            uint32_t af[2][4];
            #pragma unroll
            for (int mt = 0; mt < 2; mt++) {
                int mb = wm*32 + mt*16;
                af[mt][0] = As[kb+c  ][mb+r  ];
                af[mt][1] = As[kb+c  ][mb+r+8];
                af[mt][2] = As[kb+c+4][mb+r  ];
                af[mt][3] = As[kb+c+4][mb+r+8];
            }
            #pragma unroll
            for (int nt = 0; nt < NT; nt++) {
                int nb = wn*WN + nt*8;
                uint32_t b0 = Bs[kb+c  ][nb+r];
                uint32_t b1 = Bs[kb+c+4][nb+r];
                #pragma unroll
                for (int mt = 0; mt < 2; mt++) {
                    asm volatile(
                        "mma.sync.aligned.m16n8k8.row.col.f32.tf32.tf32.f32 "
                        "{%0,%1,%2,%3}, {%4,%5,%6,%7}, {%8,%9}, {%0,%1,%2,%3};"
                        : "+f"(acc[mt][nt][0]), "+f"(acc[mt][nt][1]),
                          "+f"(acc[mt][nt][2]), "+f"(acc[mt][nt][3])
                        : "r"(af[mt][0]), "r"(af[mt][1]), "r"(af[mt][2]), "r"(af[mt][3]),
                          "r"(b0), "r"(b1));
                }
            }
        }
        __syncthreads();
    }
    int r = lane >> 2, c2 = (lane & 3)*2;
    #pragma unroll
    for (int mt = 0; mt < 2; mt++) {
        #pragma unroll
        for (int nt = 0; nt < NT; nt++) {
            int row = m0 + wm*32 + mt*16 + r;
            int col = n0 + wn*WN + nt*8 + c2;
            float bv0 = bias ? bias[col] : 0.f;
            float bv1 = bias ? bias[col+1] : 0.f;
            float v0 = alpha*acc[mt][nt][0] + bv0;
            float v1 = alpha*acc[mt][nt][1] + bv1;
            float v2 = alpha*acc[mt][nt][2] + bv0;
            float v3 = alpha*acc[mt][nt][3] + bv1;
            if (RELU) { v0=fmaxf(v0,0.f); v1=fmaxf(v1,0.f); v2=fmaxf(v2,0.f); v3=fmaxf(v3,0.f); }
            C[(long long)row*ldc + col]       = v0;
            C[(long long)row*ldc + col+1]     = v1;
            C[(long long)(row+8)*ldc + col]   = v2;
            C[(long long)(row+8)*ldc + col+1] = v3;
        }
    }
}

// ---------- small kernels ----------
__global__ void k_buildh(const float* __restrict__ fc1o, const float* __restrict__ cls) {
    long long idx = blockIdx.x*256ll + threadIdx.x;
    if (idx >= 2ll*NSEQ*DM) return;
    int c = (int)(idx % DM); long long r = idx / DM; int b = (int)(r / NSEQ); int i = (int)(r % NSEQ);
    float v;
    if (i == 0) v = cls[c];
    else { int t = i-1; if (t >= NTOK) t -= NTOK; v = fc1o[((long long)b*NTOK + t)*DM + c]; }
    d_h[idx] = v;
}

__global__ void k_lnpad(const float* __restrict__ w, const float* __restrict__ bia) {
    int r = blockIdx.x; int b = r / NPAD, rr = r % NPAD;
    float* o = d_xln + (long long)r*DM;
    int t = threadIdx.x;
    if (rr < PADF) { o[t] = 0.f; o[t+256] = 0.f; return; }
    const float* in = d_h + ((long long)b*NSEQ + rr - PADF)*DM;
    __shared__ float red[256];
    float v0 = in[t], v1 = in[t+256];
    red[t] = v0+v1; __syncthreads();
    for (int s = 128; s > 0; s >>= 1) { if (t < s) red[t] += red[t+s]; __syncthreads(); }
    float mu = red[0]*(1.f/DM); __syncthreads();
    float e0 = v0-mu, e1 = v1-mu;
    red[t] = e0*e0+e1*e1; __syncthreads();
    for (int s = 128; s > 0; s >>= 1) { if (t < s) red[t] += red[t+s]; __syncthreads(); }
    float rstd = rsqrtf(red[0]*(1.f/DM) + 1e-5f);
    o[t]     = e0*rstd*w[t]     + bia[t];
    o[t+256] = e1*rstd*w[t+256] + bia[t+256];
}

__global__ void k_splitqkv() {
    long long idx = blockIdx.x*256ll + threadIdx.x;
    if (idx >= 2ll*NPAD*DM) return;
    int c = (int)(idx % DM);
    long long bn = idx / DM;
    int hh = c >> 6, dd = c & 63;
    int b = (int)(bn / NPAD), n = (int)(bn % NPAD);
    long long src = bn*QW + c;
    long long dst = (((long long)(b*8+hh)*NPAD) + n)*HD + dd;
    d_q[dst] = d_qkv[src];
    d_k[dst] = d_qkv[src + DM];
    d_v[dst] = d_qkv[src + 2*DM];
}

__global__ void k_lm() {
    int z = blockIdx.y, j = blockIdx.x, dd = threadIdx.x;
    const float* q = d_q + ((long long)z*NPAD + j*64)*HD + dd;
    const float* k = d_k + ((long long)z*NPAD + j*64)*HD + dd;
    float sq = 0.f, sk = 0.f;
    #pragma unroll 8
    for (int i = 0; i < 64; i++) { sq += q[i*HD]; sk += k[i*HD]; }
    d_ql[(z*NLM+j)*HD+dd] = sq*(1.f/64.f);
    d_kl[(z*NLM+j)*HD+dd] = sk*(1.f/64.f);
}

__global__ void k_sm(float* __restrict__ p, int L) {
    p += (long long)blockIdx.x * L;
    int t = threadIdx.x;
    __shared__ float red[256];
    float m = -1e30f;
    for (int i = t; i < L; i += 256) m = fmaxf(m, p[i]);
    red[t] = m; __syncthreads();
    for (int s = 128; s > 0; s >>= 1) { if (t < s) red[t] = fmaxf(red[t], red[t+s]); __syncthreads(); }
    m = red[0]; __syncthreads();
    float sum = 0.f;
    for (int i = t; i < L; i += 256) sum += __expf(p[i]-m);
    red[t] = sum; __syncthreads();
    for (int s = 128; s > 0; s >>= 1) { if (t < s) red[t] += red[t+s]; __syncthreads(); }
    float inv = 1.f/red[0];
    for (int i = t; i < L; i += 256) p[i] = __expf(p[i]-m)*inv;
}

__global__ void k_init() { d_sc[0] = 0; d_sc[1] = 0; }

__global__ void k_rmax() {
    int mb = blockIdx.x >> 8, i = blockIdx.x & 255, t = threadIdx.x;
    __shared__ float red[256];
    red[t] = fabsf(d_a2[((long long)mb*256+i)*256 + t]); __syncthreads();
    for (int s = 128; s > 0; s >>= 1) { if (t < s) red[t] += red[t+s]; __syncthreads(); }
    if (t == 0) atomicMax(&d_sc[0], __float_as_int(red[0]));
}

__global__ void k_cmax() {
    int mb = blockIdx.x, j = threadIdx.x;
    float s = 0.f;
    for (int i = 0; i < 256; i++) s += fabsf(d_a2[((long long)mb*256+i)*256 + j]);
    atomicMax(&d_sc[1], __float_as_int(s));
}

__global__ void k_tz() {
    long long idx = blockIdx.x*256ll + threadIdx.x;
    if (idx >= (long long)BH*65536) return;
    int mb = (int)(idx >> 16); int r = (int)((idx >> 8) & 255); int c = (int)(idx & 255);
    float sc = __int_as_float(d_sc[0]) * __int_as_float(d_sc[1]);
    d_z[idx] = d_a2[(long long)mb*65536 + (long long)c*256 + r] / sc;
}

__global__ void k_red() {
    int idx = blockIdx.x*256 + threadIdx.x;
    if (idx >= BH*NLM*HD) return;
    float s = 0.f;
    #pragma unroll
    for (int p = 0; p < NSPL; p++) s += d_part[(long long)p*BH*NLM*HD + idx];
    d_t3[idx] = s;
}

__global__ void k_dw(const float* __restrict__ w) {
    int z = blockIdx.y; int b = z >> 3, hh = z & 7;
    int i = blockIdx.x*4 + threadIdx.y;
    int dd = threadIdx.x;
    const float* v = d_v + (long long)z*NPAD*HD + dd;
    float s = 0.f;
    #pragma unroll
    for (int tp = 0; tp < 33; tp++) {
        int ii = i + tp - 16;
        if (ii >= 0 && ii < NPAD) s += w[hh*33+tp] * v[(long long)ii*HD];
    }
    d_ao[((long long)b*NPAD + i)*DM + hh*HD + dd] += s;
}

__global__ void k_radd() {
    long long idx = blockIdx.x*256ll + threadIdx.x;
    if (idx >= 2ll*NSEQ*DM) return;
    int c = (int)(idx % DM); long long r = idx / DM; int b = (int)(r / NSEQ); int i = (int)(r % NSEQ);
    d_h[idx] += d_xln[((long long)b*NPAD + PADF + i)*DM + c];
}

__global__ void k_ppeg(const float* __restrict__ w7, const float* __restrict__ b7,
                       const float* __restrict__ w5, const float* __restrict__ b5,
                       const float* __restrict__ w3, const float* __restrict__ b3) {
    int p = blockIdx.x, b = blockIdx.y, c = threadIdx.x;
    int r = p / GR, ww = p % GR;
    const float* base = d_h + ((long long)b*NSEQ + 1)*DM + c;
    float acc = base[(long long)p*DM] + b7[c] + b5[c] + b3[c];
    for (int i = 0; i < 7; i++) {
        int rr = r + i - 3; if (rr < 0 || rr >= GR) continue;
        for (int j = 0; j < 7; j++) {
            int cc = ww + j - 3; if (cc < 0 || cc >= GR) continue;
            float x = base[(long long)(rr*GR+cc)*DM];
            acc += w7[c*49 + i*7 + j] * x;
            if (i >= 1 && i < 6 && j >= 1 && j < 6) acc += w5[c*25 + (i-1)*5 + (j-1)] * x;
            if (i >= 2 && i < 5 && j >= 2 && j < 5) acc += w3[c*9 + (i-2)*3 + (j-2)] * x;
        }
    }
    d_xln[((long long)b*NFEAT + p)*DM + c] = acc;
}

__global__ void k_ppcp() {
    long long idx = blockIdx.x*256ll + threadIdx.x;
    if (idx >= 2ll*NFEAT*DM) return;
    int c = (int)(idx % DM); long long r = idx / DM; int b = (int)(r / NFEAT); int p = (int)(r % NFEAT);
    d_h[((long long)b*NSEQ + 1 + p)*DM + c] = d_xln[idx];
}

__global__ void k_head(const float* __restrict__ nw, const float* __restrict__ nb,
                       const float* __restrict__ f2w, const float* __restrict__ f2b,
                       float* __restrict__ out) {
    int b = blockIdx.x, t = threadIdx.x;
    const float* x = d_h + (long long)b*NSEQ*DM;
    __shared__ float red[256];
    float v0 = x[t], v1 = x[t+256];
    red[t] = v0+v1; __syncthreads();
    for (int s = 128; s > 0; s >>= 1) { if (t < s) red[t] += red[t+s]; __syncthreads(); }
    float mu = red[0]*(1.f/DM); __syncthreads();
    float e0 = v0-mu, e1 = v1-mu;
    red[t] = e0*e0+e1*e1; __syncthreads();
    for (int s = 128; s > 0; s >>= 1) { if (t < s) red[t] += red[t+s]; __syncthreads(); }
    float rstd = rsqrtf(red[0]*(1.f/DM) + 1e-5f);
    __syncthreads();
    float n0 = e0*rstd*nw[t] + nb[t], n1 = e1*rstd*nw[t+256] + nb[t+256];
    for (int j = 0; j < 2; j++) {
        red[t] = n0*f2w[j*DM+t] + n1*f2w[j*DM+t+256]; __syncthreads();
        for (int s = 128; s > 0; s >>= 1) { if (t < s) red[t] += red[t+s]; __syncthreads(); }
        if (t == 0) out[b*2+j] = red[0] + f2b[j];
        __syncthreads();
    }
}

// ---------- host wrapper ----------
static inline void TK(int TB, int RELU, int DB,
                      const float* A, const float* B, float* C, const float* bias,
                      int M, int N, int K, int lda, int ldb, int ldc, float al, float cd,
                      int Z, int zm,
                      long long a1, long long a2, long long b1, long long b2,
                      long long c1, long long c2) {
    if (N % 128 == 0) {
        dim3 g(N/128, M/128, Z);
        if (TB && RELU) tk<1,1,128,0><<<g,256>>>(A,B,C,bias,M,N,K,lda,ldb,ldc,al,cd,zm,a1,a2,b1,b2,c1,c2);
        else if (TB)    tk<1,0,128,0><<<g,256>>>(A,B,C,bias,M,N,K,lda,ldb,ldc,al,cd,zm,a1,a2,b1,b2,c1,c2);
        else if (DB)    tk<0,0,128,1><<<g,256>>>(A,B,C,bias,M,N,K,lda,ldb,ldc,al,cd,zm,a1,a2,b1,b2,c1,c2);
        else            tk<0,0,128,0><<<g,256>>>(A,B,C,bias,M,N,K,lda,ldb,ldc,al,cd,zm,a1,a2,b1,b2,c1,c2);
    } else {
        dim3 g(N/64, M/128, Z);
        tk<0,0,64,0><<<g,256>>>(A,B,C,bias,M,N,K,lda,ldb,ldc,al,cd,zm,a1,a2,b1,b2,c1,c2);
    }
}

extern "C" void kernel_launch(void* const* d_in, const int* in_sizes, int n_in,
                              void* d_out, int out_size) {
    const float* x    = (const float*)d_in[0];
    const float* fc1w = (const float*)d_in[1];
    const float* fc1b = (const float*)d_in[2];
    const float* cls  = (const float*)d_in[3];
    const float* lnw  = (const float*)d_in[4];
    const float* lnb  = (const float*)d_in[5];
    const float* qkvw = (const float*)d_in[6];
    const float* qkvb = (const float*)d_in[7];
    const float* aow  = (const float*)d_in[8];
    const float* aob  = (const float*)d_in[9];
    const float* rcw  = (const float*)d_in[10];
    const float* w7 = (const float*)d_in[11]; const float* b7 = (const float*)d_in[12];
    const float* w5 = (const float*)d_in[13]; const float* b5 = (const float*)d_in[14];
    const float* w3 = (const float*)d_in[15]; const float* b3 = (const float*)d_in[16];
    const float* nw = (const float*)d_in[17]; const float* nb = (const float*)d_in[18];
    const float* f2w = (const float*)d_in[19]; const float* f2b = (const float*)d_in[20];
    float* out = (float*)d_out;

    float *xln, *qkv, *sbuf, *ao, *q, *k, *v, *part;
    float *ql, *kl, *a2, *z, *z2, *az, *tt, *uu, *t3, *w;
    cudaGetSymbolAddress((void**)&xln, d_xln);
    cudaGetSymbolAddress((void**)&qkv, d_qkv);
    cudaGetSymbolAddress((void**)&sbuf, d_sbuf);
    cudaGetSymbolAddress((void**)&ao, d_ao);
    cudaGetSymbolAddress((void**)&q, d_q);
    cudaGetSymbolAddress((void**)&k, d_k);
    cudaGetSymbolAddress((void**)&v, d_v);
    cudaGetSymbolAddress((void**)&part, d_part);
    cudaGetSymbolAddress((void**)&ql, d_ql);
    cudaGetSymbolAddress((void**)&kl, d_kl);
    cudaGetSymbolAddress((void**)&a2, d_a2);
    cudaGetSymbolAddress((void**)&z, d_z);
    cudaGetSymbolAddress((void**)&z2, d_z2);
    cudaGetSymbolAddress((void**)&az, d_az);
    cudaGetSymbolAddress((void**)&tt, d_tt);
    cudaGetSymbolAddress((void**)&uu, d_uu);
    cudaGetSymbolAddress((void**)&t3, d_t3);
    cudaGetSymbolAddress((void**)&w, d_w);

    const long long SQ  = (long long)NPAD*QW;
    const long long SD  = (long long)NPAD*DM;
    const long long SH  = (long long)NPAD*HD;
    const long long SS3 = (long long)NLM*NPAD;
    const long long SS1 = (long long)NPAD*NLM;

    // fc1 + relu -> sbuf (32000,512); then assemble token stream h
    TK(1,1,0, x, fc1w, sbuf, fc1b, 2*NTOK, DM, 1024, 1024, 1024, DM, 1.f, 0.f, 1,1, 0,0,0,0,0,0);
    k_buildh<<<(int)((2ll*NSEQ*DM+255)/256),256>>>(sbuf, cls);

    for (int l = 0; l < 2; l++) {
        k_lnpad<<<2*NPAD,256>>>(lnw + l*DM, lnb + l*DM);
        TK(1,0,0, xln, qkvw + (long long)l*QW*DM, qkv, qkvb + l*QW,
           NPAD, QW, DM, DM, DM, QW, 1.f, 0.f, 2,2, SD,0, 0,0, SQ,0);
        k_splitqkv<<<(int)((2ll*NPAD*DM+255)/256),256>>>();
        k_lm<<<dim3(256,16),64>>>();
        // attn2 = softmax(0.125 * ql @ kl^T)
        TK(1,0,0, ql, kl, a2, 0, NLM, NLM, HD, HD, HD, NLM, 0.125f, 0.f, BH,BH,
           NLM*HD,0, NLM*HD,0, NLM*NLM,0);
        k_sm<<<BH*NLM,256>>>(a2, NLM);
        // pinv(attn2): z0 = a2^T/scale, then 6 Newton-Schulz iters (elementwise fused into B-loads)
        k_init<<<1,1>>>();
        k_rmax<<<BH*NLM,256>>>();
        k_cmax<<<BH,256>>>();
        k_tz<<<(BH*65536+255)/256,256>>>();
        float* zc = z; float* zn = z2;
        for (int it = 0; it < 6; it++) {
            TK(0,0,0, a2, zc, az, 0, NLM,NLM,NLM, NLM,NLM,NLM, 1.f, 0.f, BH,BH, 65536,0,65536,0,65536,0);
            TK(0,0,1, az, az, tt, 0, NLM,NLM,NLM, NLM,NLM,NLM, 1.f, 7.f, BH,BH, 65536,0,65536,0,65536,0);
            TK(0,0,1, az, tt, uu, 0, NLM,NLM,NLM, NLM,NLM,NLM, 1.f, 15.f, BH,BH, 65536,0,65536,0,65536,0);
            TK(0,0,1, zc, uu, zn, 0, NLM,NLM,NLM, NLM,NLM,NLM, 0.25f, 13.f, BH,BH, 65536,0,65536,0,65536,0);
            float* sw = zc; zc = zn; zn = sw;
        }
        // S3 = softmax(0.125 * ql @ k^T)   [z][256][16384]
        TK(1,0,0, ql, k, sbuf, 0, NLM, NPAD, HD, HD, HD, NPAD, 0.125f, 0.f, BH,BH,
           NLM*HD,0, SH,0, SS3,0);
        k_sm<<<BH*NLM,256>>>(sbuf, NPAD);
        // t3 = S3 @ v  split-K over 32 chunks of 512
        TK(0,0,0, sbuf, v, part, 0, NLM, HD, KSPL, NPAD, HD, HD, 1.f, 0.f, BH*NSPL, BH,
           SS3, 512, SH, (long long)KSPL*HD, (long long)NLM*HD, (long long)BH*NLM*HD);
        k_red<<<(BH*NLM*HD+255)/256,256>>>();
        // w = pinv @ t3
        TK(0,0,0, zc, t3, w, 0, NLM, HD, NLM, NLM, HD, HD, 1.f, 0.f, BH,BH,
           65536,0, NLM*HD,0, NLM*HD,0);
        // S1 = softmax(0.125 * q @ kl^T)  [z][16384][256]
        TK(1,0,0, q, kl, sbuf, 0, NPAD, NLM, HD, HD, HD, NLM, 0.125f, 0.f, BH,BH,
           SH,0, NLM*HD,0, SS1,0);
        k_sm<<<BH*NPAD,256>>>(sbuf, NLM);
        // ao = S1 @ w  -> [b][n][h*64+d]
        TK(0,0,0, sbuf, w, ao, 0, NPAD, HD, NLM, NLM, HD, DM, 1.f, 0.f, BH,8,
           SS1, 8ll*SS1, NLM*HD, 8ll*NLM*HD, HD, SD);
        // depthwise residual conv over v
        k_dw<<<dim3(NPAD/4,BH),dim3(64,4)>>>(rcw + l*264);
        // out projection + residual
        TK(1,0,0, ao, aow + (long long)l*DM*DM, xln, aob + l*DM,
           NPAD, DM, DM, DM, DM, DM, 1.f, 0.f, 2,2, SD,0, 0,0, SD,0);
        k_radd<<<(int)((2ll*NSEQ*DM+255)/256),256>>>();
        if (l == 0) {
            k_ppeg<<<dim3(NFEAT,2),512>>>(w7,b7,w5,b5,w3,b3);
            k_ppcp<<<(int)((2ll*NFEAT*DM+255)/256),256>>>();
        }
    }
    k_head<<<2,256>>>(nw, nb, f2w, f2b, out);
}

// round 10
// speedup vs baseline: 3.7095x; 1.7942x over previous
#include <cuda_runtime.h>
#include <math.h>
#include <stdint.h>

#define NSEQ 16130
#define NPAD 16384
#define PADF 254
#define NLM 256
#define DM 512
#define QW 1536
#define HD 64
#define BH 16
#define NTOK 16000
#define NFEAT 16129
#define GR 127
#define NSPL 32
#define KSPL 512

// ---------- static scratch ----------
__device__ float d_h[2ll*NSEQ*DM];
__device__ float d_xln[2ll*NPAD*DM];
__device__ float d_qkv[2ll*NPAD*QW];
__device__ float d_sbuf[(long long)BH*NPAD*NLM];
__device__ float d_ao[2ll*NPAD*DM];
__device__ float d_q[(long long)BH*NPAD*HD];
__device__ float d_k[(long long)BH*NPAD*HD];
__device__ float d_v[(long long)BH*NPAD*HD];
__device__ float d_part[(long long)NSPL*BH*NLM*HD];
__device__ float d_ql[BH*NLM*HD], d_kl[BH*NLM*HD];
__device__ float d_a2[BH*NLM*NLM], d_z[BH*NLM*NLM], d_z2[BH*NLM*NLM];
__device__ float d_az[BH*NLM*NLM], d_tt[BH*NLM*NLM], d_uu[BH*NLM*NLM];
__device__ float d_t3[BH*NLM*HD], d_w[BH*NLM*HD];
__device__ int d_sc[2];

// ---------- TF32 tensor-core GEMM, register-prefetch double-buffered ----------
// C = alpha * A @ op(B) (+bias) (+relu).  TB: B is [N][K] row-major -> B^T.
// DB: B' = cd*I - B applied at fragment load (TB=0 only).
// Requires M%128==0, N%BN==0, K%16==0, lda/ldb%4==0.
template<int TB, int RELU, int BN, int DB>
__global__ void __launch_bounds__(256) tk(
    const float* __restrict__ A, const float* __restrict__ B,
    float* __restrict__ C, const float* __restrict__ bias,
    int M, int N, int K, int lda, int ldb, int ldc, float alpha, float cd,
    int zm, long long sa1, long long sa2, long long sb1, long long sb2,
    long long sc1, long long sc2)
{
    int z = blockIdx.z, z1 = z % zm, z2 = z / zm;
    A += (long long)z1*sa1 + (long long)z2*sa2;
    B += (long long)z1*sb1 + (long long)z2*sb2;
    C += (long long)z1*sc1 + (long long)z2*sc2;

    __shared__ float As[2][128][20];
    constexpr int BS_R = TB ? BN : 16;
    constexpr int BS_C = TB ? 20 : (BN + 8);
    __shared__ float Bs[2][BS_R][BS_C];
    constexpr int NB4 = BN/64;

    int tid = threadIdx.x, lane = tid & 31, warp = tid >> 5;
    int wm = warp & 3, wn = warp >> 2;          // 4x2 warp grid
    constexpr int WN = BN/2, NT = WN/8;
    int m0 = blockIdx.y*128, n0 = blockIdx.x*BN;

    float acc[2][NT][4];
    #pragma unroll
    for (int a = 0; a < 2; a++)
        #pragma unroll
        for (int b = 0; b < NT; b++)
            #pragma unroll
            for (int cc = 0; cc < 4; cc++) acc[a][b][cc] = 0.f;

    float4 ra[2], rb[NB4];

    auto ldgT = [&](int k0) {
        #pragma unroll
        for (int j = 0; j < 2; j++) {
            int id = tid + j*256;
            int mm = id >> 2, kc = (id & 3)*4;
            ra[j] = *(const float4*)(A + (long long)(m0+mm)*lda + k0 + kc);
        }
        if (TB) {
            #pragma unroll
            for (int j = 0; j < NB4; j++) {
                int id = tid + j*256;
                int nn = id >> 2, kc = (id & 3)*4;
                rb[j] = *(const float4*)(B + (long long)(n0+nn)*ldb + k0 + kc);
            }
        } else {
            #pragma unroll
            for (int j = 0; j < NB4; j++) {
                int id = tid + j*256;
                int kk = id / (BN/4), nc = (id % (BN/4))*4;
                rb[j] = *(const float4*)(B + (long long)(k0+kk)*ldb + n0 + nc);
            }
        }
    };
    auto stsT = [&](int st) {
        #pragma unroll
        for (int j = 0; j < 2; j++) {
            int id = tid + j*256;
            int mm = id >> 2, kc = (id & 3)*4;
            *(float4*)&As[st][mm][kc] = ra[j];
        }
        if (TB) {
            #pragma unroll
            for (int j = 0; j < NB4; j++) {
                int id = tid + j*256;
                int nn = id >> 2, kc = (id & 3)*4;
                *(float4*)&Bs[st][nn][kc] = rb[j];
            }
        } else {
            #pragma unroll
            for (int j = 0; j < NB4; j++) {
                int id = tid + j*256;
                int kk = id / (BN/4), nc = (id % (BN/4))*4;
                *(float4*)&Bs[st][kk][nc] = rb[j];
            }
        }
    };

    int nk = K >> 4;
    ldgT(0);
    stsT(0);
    __syncthreads();

    for (int kt = 0; kt < nk; kt++) {
        int cur = kt & 1;
        if (kt + 1 < nk) ldgT((kt+1)*16);   // prefetch next tile; binds at stsT below
        int k0 = kt*16;
        int r = lane >> 2, c = lane & 3;
        #pragma unroll
        for (int ks = 0; ks < 2; ks++) {
            int kb = ks*8;
            uint32_t af[2][4];
            #pragma unroll
            for (int mt = 0; mt < 2; mt++) {
                int mb = wm*32 + mt*16;
                af[mt][0] = __float_as_uint(As[cur][mb+r  ][kb+c  ]);
                af[mt][1] = __float_as_uint(As[cur][mb+r+8][kb+c  ]);
                af[mt][2] = __float_as_uint(As[cur][mb+r  ][kb+c+4]);
                af[mt][3] = __float_as_uint(As[cur][mb+r+8][kb+c+4]);
            }
            #pragma unroll
            for (int nt = 0; nt < NT; nt++) {
                int nb = wn*WN + nt*8;
                uint32_t b0, b1;
                if (TB) {
                    b0 = __float_as_uint(Bs[cur][nb+r][kb+c  ]);
                    b1 = __float_as_uint(Bs[cur][nb+r][kb+c+4]);
                } else {
                    float f0 = Bs[cur][kb+c  ][nb+r];
                    float f1 = Bs[cur][kb+c+4][nb+r];
                    if (DB) {
                        int ng = n0 + nb + r;
                        f0 = ((k0+kb+c  ) == ng ? cd : 0.f) - f0;
                        f1 = ((k0+kb+c+4) == ng ? cd : 0.f) - f1;
                    }
                    b0 = __float_as_uint(f0);
                    b1 = __float_as_uint(f1);
                }
                #pragma unroll
                for (int mt = 0; mt < 2; mt++) {
                    asm volatile(
                        "mma.sync.aligned.m16n8k8.row.col.f32.tf32.tf32.f32 "
                        "{%0,%1,%2,%3}, {%4,%5,%6,%7}, {%8,%9}, {%0,%1,%2,%3};"
                        : "+f"(acc[mt][nt][0]), "+f"(acc[mt][nt][1]),
                          "+f"(acc[mt][nt][2]), "+f"(acc[mt][nt][3])
                        : "r"(af[mt][0]), "r"(af[mt][1]), "r"(af[mt][2]), "r"(af[mt][3]),
                          "r"(b0), "r"(b1));
                }
            }
        }
        if (kt + 1 < nk) stsT(cur ^ 1);     // writes buffer nobody reads this iter
        __syncthreads();
    }
    int r = lane >> 2, c2 = (lane & 3)*2;
    #pragma unroll
    for (int mt = 0; mt < 2; mt++) {
        #pragma unroll
        for (int nt = 0; nt < NT; nt++) {
            int row = m0 + wm*32 + mt*16 + r;
            int col = n0 + wn*WN + nt*8 + c2;
            float bv0 = bias ? bias[col] : 0.f;
            float bv1 = bias ? bias[col+1] : 0.f;
            float v0 = alpha*acc[mt][nt][0] + bv0;
            float v1 = alpha*acc[mt][nt][1] + bv1;
            float v2 = alpha*acc[mt][nt][2] + bv0;
            float v3 = alpha*acc[mt][nt][3] + bv1;
            if (RELU) { v0=fmaxf(v0,0.f); v1=fmaxf(v1,0.f); v2=fmaxf(v2,0.f); v3=fmaxf(v3,0.f); }
            C[(long long)row*ldc + col]       = v0;
            C[(long long)row*ldc + col+1]     = v1;
            C[(long long)(row+8)*ldc + col]   = v2;
            C[(long long)(row+8)*ldc + col+1] = v3;
        }
    }
}

// ---------- small kernels ----------
__global__ void k_buildh(const float* __restrict__ fc1o, const float* __restrict__ cls) {
    long long idx = blockIdx.x*256ll + threadIdx.x;
    if (idx >= 2ll*NSEQ*DM) return;
    int c = (int)(idx % DM); long long r = idx / DM; int b = (int)(r / NSEQ); int i = (int)(r % NSEQ);
    float v;
    if (i == 0) v = cls[c];
    else { int t = i-1; if (t >= NTOK) t -= NTOK; v = fc1o[((long long)b*NTOK + t)*DM + c]; }
    d_h[idx] = v;
}

__global__ void k_lnpad(const float* __restrict__ w, const float* __restrict__ bia) {
    int r = blockIdx.x; int b = r / NPAD, rr = r % NPAD;
    float* o = d_xln + (long long)r*DM;
    int t = threadIdx.x;
    if (rr < PADF) { o[t] = 0.f; o[t+256] = 0.f; return; }
    const float* in = d_h + ((long long)b*NSEQ + rr - PADF)*DM;
    __shared__ float red[256];
    float v0 = in[t], v1 = in[t+256];
    red[t] = v0+v1; __syncthreads();
    for (int s = 128; s > 0; s >>= 1) { if (t < s) red[t] += red[t+s]; __syncthreads(); }
    float mu = red[0]*(1.f/DM); __syncthreads();
    float e0 = v0-mu, e1 = v1-mu;
    red[t] = e0*e0+e1*e1; __syncthreads();
    for (int s = 128; s > 0; s >>= 1) { if (t < s) red[t] += red[t+s]; __syncthreads(); }
    float rstd = rsqrtf(red[0]*(1.f/DM) + 1e-5f);
    o[t]     = e0*rstd*w[t]     + bia[t];
    o[t+256] = e1*rstd*w[t+256] + bia[t+256];
}

__global__ void k_splitqkv() {
    long long idx = blockIdx.x*256ll + threadIdx.x;
    if (idx >= 2ll*NPAD*DM) return;
    int c = (int)(idx % DM);
    long long bn = idx / DM;
    int hh = c >> 6, dd = c & 63;
    int b = (int)(bn / NPAD), n = (int)(bn % NPAD);
    long long src = bn*QW + c;
    long long dst = (((long long)(b*8+hh)*NPAD) + n)*HD + dd;
    d_q[dst] = d_qkv[src];
    d_k[dst] = d_qkv[src + DM];
    d_v[dst] = d_qkv[src + 2*DM];
}

__global__ void k_lm() {
    int z = blockIdx.y, j = blockIdx.x, dd = threadIdx.x;
    const float* q = d_q + ((long long)z*NPAD + j*64)*HD + dd;
    const float* k = d_k + ((long long)z*NPAD + j*64)*HD + dd;
    float sq = 0.f, sk = 0.f;
    #pragma unroll 8
    for (int i = 0; i < 64; i++) { sq += q[i*HD]; sk += k[i*HD]; }
    d_ql[(z*NLM+j)*HD+dd] = sq*(1.f/64.f);
    d_kl[(z*NLM+j)*HD+dd] = sk*(1.f/64.f);
}

__global__ void k_sm(float* __restrict__ p, int L) {
    p += (long long)blockIdx.x * L;
    int t = threadIdx.x;
    __shared__ float red[256];
    float m = -1e30f;
    for (int i = t; i < L; i += 256) m = fmaxf(m, p[i]);
    red[t] = m; __syncthreads();
    for (int s = 128; s > 0; s >>= 1) { if (t < s) red[t] = fmaxf(red[t], red[t+s]); __syncthreads(); }
    m = red[0]; __syncthreads();
    float sum = 0.f;
    for (int i = t; i < L; i += 256) sum += __expf(p[i]-m);
    red[t] = sum; __syncthreads();
    for (int s = 128; s > 0; s >>= 1) { if (t < s) red[t] += red[t+s]; __syncthreads(); }
    float inv = 1.f/red[0];
    for (int i = t; i < L; i += 256) p[i] = __expf(p[i]-m)*inv;
}

__global__ void k_init() { d_sc[0] = 0; d_sc[1] = 0; }

__global__ void k_rmax() {
    int mb = blockIdx.x >> 8, i = blockIdx.x & 255, t = threadIdx.x;
    __shared__ float red[256];
    red[t] = fabsf(d_a2[((long long)mb*256+i)*256 + t]); __syncthreads();
    for (int s = 128; s > 0; s >>= 1) { if (t < s) red[t] += red[t+s]; __syncthreads(); }
    if (t == 0) atomicMax(&d_sc[0], __float_as_int(red[0]));
}

__global__ void k_cmax() {
    int mb = blockIdx.x, j = threadIdx.x;
    float s = 0.f;
    for (int i = 0; i < 256; i++) s += fabsf(d_a2[((long long)mb*256+i)*256 + j]);
    atomicMax(&d_sc[1], __float_as_int(s));
}

__global__ void k_tz() {
    long long idx = blockIdx.x*256ll + threadIdx.x;
    if (idx >= (long long)BH*65536) return;
    int mb = (int)(idx >> 16); int r = (int)((idx >> 8) & 255); int c = (int)(idx & 255);
    float sc = __int_as_float(d_sc[0]) * __int_as_float(d_sc[1]);
    d_z[idx] = d_a2[(long long)mb*65536 + (long long)c*256 + r] / sc;
}

__global__ void k_red() {
    int idx = blockIdx.x*256 + threadIdx.x;
    if (idx >= BH*NLM*HD) return;
    float s = 0.f;
    #pragma unroll
    for (int p = 0; p < NSPL; p++) s += d_part[(long long)p*BH*NLM*HD + idx];
    d_t3[idx] = s;
}

__global__ void k_dw(const float* __restrict__ w) {
    int z = blockIdx.y; int b = z >> 3, hh = z & 7;
    int i = blockIdx.x*4 + threadIdx.y;
    int dd = threadIdx.x;
    const float* v = d_v + (long long)z*NPAD*HD + dd;
    float s = 0.f;
    #pragma unroll
    for (int tp = 0; tp < 33; tp++) {
        int ii = i + tp - 16;
        if (ii >= 0 && ii < NPAD) s += w[hh*33+tp] * v[(long long)ii*HD];
    }
    d_ao[((long long)b*NPAD + i)*DM + hh*HD + dd] += s;
}

__global__ void k_radd() {
    long long idx = blockIdx.x*256ll + threadIdx.x;
    if (idx >= 2ll*NSEQ*DM) return;
    int c = (int)(idx % DM); long long r = idx / DM; int b = (int)(r / NSEQ); int i = (int)(r % NSEQ);
    d_h[idx] += d_xln[((long long)b*NPAD + PADF + i)*DM + c];
}

__global__ void k_ppeg(const float* __restrict__ w7, const float* __restrict__ b7,
                       const float* __restrict__ w5, const float* __restrict__ b5,
                       const float* __restrict__ w3, const float* __restrict__ b3) {
    int p = blockIdx.x, b = blockIdx.y, c = threadIdx.x;
    int r = p / GR, ww = p % GR;
    const float* base = d_h + ((long long)b*NSEQ + 1)*DM + c;
    float acc = base[(long long)p*DM] + b7[c] + b5[c] + b3[c];
    for (int i = 0; i < 7; i++) {
        int rr = r + i - 3; if (rr < 0 || rr >= GR) continue;
        for (int j = 0; j < 7; j++) {
            int cc = ww + j - 3; if (cc < 0 || cc >= GR) continue;
            float x = base[(long long)(rr*GR+cc)*DM];
            acc += w7[c*49 + i*7 + j] * x;
            if (i >= 1 && i < 6 && j >= 1 && j < 6) acc += w5[c*25 + (i-1)*5 + (j-1)] * x;
            if (i >= 2 && i < 5 && j >= 2 && j < 5) acc += w3[c*9 + (i-2)*3 + (j-2)] * x;
        }
    }
    d_xln[((long long)b*NFEAT + p)*DM + c] = acc;
}

__global__ void k_ppcp() {
    long long idx = blockIdx.x*256ll + threadIdx.x;
    if (idx >= 2ll*NFEAT*DM) return;
    int c = (int)(idx % DM); long long r = idx / DM; int b = (int)(r / NFEAT); int p = (int)(r % NFEAT);
    d_h[((long long)b*NSEQ + 1 + p)*DM + c] = d_xln[idx];
}

__global__ void k_head(const float* __restrict__ nw, const float* __restrict__ nb,
                       const float* __restrict__ f2w, const float* __restrict__ f2b,
                       float* __restrict__ out) {
    int b = blockIdx.x, t = threadIdx.x;
    const float* x = d_h + (long long)b*NSEQ*DM;
    __shared__ float red[256];
    float v0 = x[t], v1 = x[t+256];
    red[t] = v0+v1; __syncthreads();
    for (int s = 128; s > 0; s >>= 1) { if (t < s) red[t] += red[t+s]; __syncthreads(); }
    float mu = red[0]*(1.f/DM); __syncthreads();
    float e0 = v0-mu, e1 = v1-mu;
    red[t] = e0*e0+e1*e1; __syncthreads();
    for (int s = 128; s > 0; s >>= 1) { if (t < s) red[t] += red[t+s]; __syncthreads(); }
    float rstd = rsqrtf(red[0]*(1.f/DM) + 1e-5f);
    __syncthreads();
    float n0 = e0*rstd*nw[t] + nb[t], n1 = e1*rstd*nw[t+256] + nb[t+256];
    for (int j = 0; j < 2; j++) {
        red[t] = n0*f2w[j*DM+t] + n1*f2w[j*DM+t+256]; __syncthreads();
        for (int s = 128; s > 0; s >>= 1) { if (t < s) red[t] += red[t+s]; __syncthreads(); }
        if (t == 0) out[b*2+j] = red[0] + f2b[j];
        __syncthreads();
    }
}

// ---------- host wrapper ----------
static inline void TK(int TB, int RELU, int DB,
                      const float* A, const float* B, float* C, const float* bias,
                      int M, int N, int K, int lda, int ldb, int ldc, float al, float cd,
                      int Z, int zm,
                      long long a1, long long a2, long long b1, long long b2,
                      long long c1, long long c2) {
    if (N % 128 == 0) {
        dim3 g(N/128, M/128, Z);
        if (TB && RELU) tk<1,1,128,0><<<g,256>>>(A,B,C,bias,M,N,K,lda,ldb,ldc,al,cd,zm,a1,a2,b1,b2,c1,c2);
        else if (TB)    tk<1,0,128,0><<<g,256>>>(A,B,C,bias,M,N,K,lda,ldb,ldc,al,cd,zm,a1,a2,b1,b2,c1,c2);
        else if (DB)    tk<0,0,128,1><<<g,256>>>(A,B,C,bias,M,N,K,lda,ldb,ldc,al,cd,zm,a1,a2,b1,b2,c1,c2);
        else            tk<0,0,128,0><<<g,256>>>(A,B,C,bias,M,N,K,lda,ldb,ldc,al,cd,zm,a1,a2,b1,b2,c1,c2);
    } else {
        dim3 g(N/64, M/128, Z);
        tk<0,0,64,0><<<g,256>>>(A,B,C,bias,M,N,K,lda,ldb,ldc,al,cd,zm,a1,a2,b1,b2,c1,c2);
    }
}

extern "C" void kernel_launch(void* const* d_in, const int* in_sizes, int n_in,
                              void* d_out, int out_size) {
    const float* x    = (const float*)d_in[0];
    const float* fc1w = (const float*)d_in[1];
    const float* fc1b = (const float*)d_in[2];
    const float* cls  = (const float*)d_in[3];
    const float* lnw  = (const float*)d_in[4];
    const float* lnb  = (const float*)d_in[5];
    const float* qkvw = (const float*)d_in[6];
    const float* qkvb = (const float*)d_in[7];
    const float* aow  = (const float*)d_in[8];
    const float* aob  = (const float*)d_in[9];
    const float* rcw  = (const float*)d_in[10];
    const float* w7 = (const float*)d_in[11]; const float* b7 = (const float*)d_in[12];
    const float* w5 = (const float*)d_in[13]; const float* b5 = (const float*)d_in[14];
    const float* w3 = (const float*)d_in[15]; const float* b3 = (const float*)d_in[16];
    const float* nw = (const float*)d_in[17]; const float* nb = (const float*)d_in[18];
    const float* f2w = (const float*)d_in[19]; const float* f2b = (const float*)d_in[20];
    float* out = (float*)d_out;

    float *xln, *qkv, *sbuf, *ao, *q, *k, *v, *part;
    float *ql, *kl, *a2, *z, *z2, *az, *tt, *uu, *t3, *w;
    cudaGetSymbolAddress((void**)&xln, d_xln);
    cudaGetSymbolAddress((void**)&qkv, d_qkv);
    cudaGetSymbolAddress((void**)&sbuf, d_sbuf);
    cudaGetSymbolAddress((void**)&ao, d_ao);
    cudaGetSymbolAddress((void**)&q, d_q);
    cudaGetSymbolAddress((void**)&k, d_k);
    cudaGetSymbolAddress((void**)&v, d_v);
    cudaGetSymbolAddress((void**)&part, d_part);
    cudaGetSymbolAddress((void**)&ql, d_ql);
    cudaGetSymbolAddress((void**)&kl, d_kl);
    cudaGetSymbolAddress((void**)&a2, d_a2);
    cudaGetSymbolAddress((void**)&z, d_z);
    cudaGetSymbolAddress((void**)&z2, d_z2);
    cudaGetSymbolAddress((void**)&az, d_az);
    cudaGetSymbolAddress((void**)&tt, d_tt);
    cudaGetSymbolAddress((void**)&uu, d_uu);
    cudaGetSymbolAddress((void**)&t3, d_t3);
    cudaGetSymbolAddress((void**)&w, d_w);

    const long long SQ  = (long long)NPAD*QW;
    const long long SD  = (long long)NPAD*DM;
    const long long SH  = (long long)NPAD*HD;
    const long long SS3 = (long long)NLM*NPAD;
    const long long SS1 = (long long)NPAD*NLM;

    // fc1 + relu -> sbuf (32000,512); then assemble token stream h
    TK(1,1,0, x, fc1w, sbuf, fc1b, 2*NTOK, DM, 1024, 1024, 1024, DM, 1.f, 0.f, 1,1, 0,0,0,0,0,0);
    k_buildh<<<(int)((2ll*NSEQ*DM+255)/256),256>>>(sbuf, cls);

    for (int l = 0; l < 2; l++) {
        k_lnpad<<<2*NPAD,256>>>(lnw + l*DM, lnb + l*DM);
        TK(1,0,0, xln, qkvw + (long long)l*QW*DM, qkv, qkvb + l*QW,
           NPAD, QW, DM, DM, DM, QW, 1.f, 0.f, 2,2, SD,0, 0,0, SQ,0);
        k_splitqkv<<<(int)((2ll*NPAD*DM+255)/256),256>>>();
        k_lm<<<dim3(256,16),64>>>();
        // attn2 = softmax(0.125 * ql @ kl^T)
        TK(1,0,0, ql, kl, a2, 0, NLM, NLM, HD, HD, HD, NLM, 0.125f, 0.f, BH,BH,
           NLM*HD,0, NLM*HD,0, NLM*NLM,0);
        k_sm<<<BH*NLM,256>>>(a2, NLM);
        // pinv(attn2): z0 = a2^T/scale, then 6 Newton-Schulz iters (elementwise fused into B fragment loads)
        k_init<<<1,1>>>();
        k_rmax<<<BH*NLM,256>>>();
        k_cmax<<<BH,256>>>();
        k_tz<<<(BH*65536+255)/256,256>>>();
        float* zc = z; float* zn = z2;
        for (int it = 0; it < 6; it++) {
            TK(0,0,0, a2, zc, az, 0, NLM,NLM,NLM, NLM,NLM,NLM, 1.f, 0.f, BH,BH, 65536,0,65536,0,65536,0);
            TK(0,0,1, az, az, tt, 0, NLM,NLM,NLM, NLM,NLM,NLM, 1.f, 7.f, BH,BH, 65536,0,65536,0,65536,0);
            TK(0,0,1, az, tt, uu, 0, NLM,NLM,NLM, NLM,NLM,NLM, 1.f, 15.f, BH,BH, 65536,0,65536,0,65536,0);
            TK(0,0,1, zc, uu, zn, 0, NLM,NLM,NLM, NLM,NLM,NLM, 0.25f, 13.f, BH,BH, 65536,0,65536,0,65536,0);
            float* sw = zc; zc = zn; zn = sw;
        }
        // S3 = softmax(0.125 * ql @ k^T)   [z][256][16384]
        TK(1,0,0, ql, k, sbuf, 0, NLM, NPAD, HD, HD, HD, NPAD, 0.125f, 0.f, BH,BH,
           NLM*HD,0, SH,0, SS3,0);
        k_sm<<<BH*NLM,256>>>(sbuf, NPAD);
        // t3 = S3 @ v  split-K over 32 chunks of 512
        TK(0,0,0, sbuf, v, part, 0, NLM, HD, KSPL, NPAD, HD, HD, 1.f, 0.f, BH*NSPL, BH,
           SS3, 512, SH, (long long)KSPL*HD, (long long)NLM*HD, (long long)BH*NLM*HD);
        k_red<<<(BH*NLM*HD+255)/256,256>>>();
        // w = pinv @ t3
        TK(0,0,0, zc, t3, w, 0, NLM, HD, NLM, NLM, HD, HD, 1.f, 0.f, BH,BH,
           65536,0, NLM*HD,0, NLM*HD,0);
        // S1 = softmax(0.125 * q @ kl^T)  [z][16384][256]
        TK(1,0,0, q, kl, sbuf, 0, NPAD, NLM, HD, HD, HD, NLM, 0.125f, 0.f, BH,BH,
           SH,0, NLM*HD,0, SS1,0);
        k_sm<<<BH*NPAD,256>>>(sbuf, NLM);
        // ao = S1 @ w  -> [b][n][h*64+d]
        TK(0,0,0, sbuf, w, ao, 0, NPAD, HD, NLM, NLM, HD, DM, 1.f, 0.f, BH,8,
           SS1, 8ll*SS1, NLM*HD, 8ll*NLM*HD, HD, SD);
        // depthwise residual conv over v
        k_dw<<<dim3(NPAD/4,BH),dim3(64,4)>>>(rcw + l*264);
        // out projection + residual
        TK(1,0,0, ao, aow + (long long)l*DM*DM, xln, aob + l*DM,
           NPAD, DM, DM, DM, DM, DM, 1.f, 0.f, 2,2, SD,0, 0,0, SD,0);
        k_radd<<<(int)((2ll*NSEQ*DM+255)/256),256>>>();
        if (l == 0) {
            k_ppeg<<<dim3(NFEAT,2),512>>>(w7,b7,w5,b5,w3,b3);
            k_ppcp<<<(int)((2ll*NFEAT*DM+255)/256),256>>>();
        }
    }
    k_head<<<2,256>>>(nw, nb, f2w, f2b, out);
}

// round 12
// speedup vs baseline: 4.8122x; 1.2973x over previous
#include <cuda_runtime.h>
#include <cuda_bf16.h>
#include <math.h>
#include <stdint.h>

#define NSEQ 16130
#define NPAD 16384
#define PADF 254
#define NLM 256
#define DM 512
#define QW 1536
#define HD 64
#define BH 16
#define NTOK 16000
#define NFEAT 16129
#define GR 127
#define NSPL 32
#define KSPL 512

// ---------- static scratch ----------
__device__ float d_h[2ll*NSEQ*DM];
__device__ float d_xln[2ll*NPAD*DM];
__device__ float d_qkv[2ll*NPAD*QW];
__device__ float d_sbuf[(long long)BH*NPAD*NLM];
__device__ float d_ao[2ll*NPAD*DM];
__device__ float d_q[(long long)BH*NPAD*HD];
__device__ float d_k[(long long)BH*NPAD*HD];
__device__ float d_v[(long long)BH*NPAD*HD];
__device__ float d_part[(long long)NSPL*BH*NLM*HD];
__device__ float d_ql[BH*NLM*HD], d_kl[BH*NLM*HD];
__device__ float d_a2[BH*NLM*NLM], d_z[BH*NLM*NLM], d_z2[BH*NLM*NLM];
__device__ float d_az[BH*NLM*NLM], d_tt[BH*NLM*NLM], d_uu[BH*NLM*NLM];
__device__ float d_t3[BH*NLM*HD], d_w[BH*NLM*HD];
__device__ int d_sc[2];

// ---------- BF16 tensor-core GEMM (TB only), register-prefetch double-buffered ----------
// C = alpha * A @ B^T (+bias)(+relu); A [M][K] fp32, B [N][K] fp32; converts to bf16 at STS.
// Requires M%128==0, N%128==0, K%16==0, lda/ldb%4==0.
template<int RELU>
__global__ void __launch_bounds__(256) hk(
    const float* __restrict__ A, const float* __restrict__ B,
    float* __restrict__ C, const float* __restrict__ bias,
    int M, int N, int K, int lda, int ldb, int ldc, float alpha,
    int zm, long long sa1, long long sa2, long long sb1, long long sb2,
    long long sc1, long long sc2)
{
    int z = blockIdx.z, z1 = z % zm, z2 = z / zm;
    A += (long long)z1*sa1 + (long long)z2*sa2;
    B += (long long)z1*sb1 + (long long)z2*sb2;
    C += (long long)z1*sc1 + (long long)z2*sc2;

    __shared__ __nv_bfloat16 As[2][128][24];
    __shared__ __nv_bfloat16 Bs[2][128][24];

    int tid = threadIdx.x, lane = tid & 31, warp = tid >> 5;
    int wm = warp & 3, wn = warp >> 2;          // 4x2 warp grid: warp tile 32x64
    int m0 = blockIdx.y*128, n0 = blockIdx.x*128;

    float acc[2][8][4];
    #pragma unroll
    for (int a = 0; a < 2; a++)
        #pragma unroll
        for (int b = 0; b < 8; b++)
            #pragma unroll
            for (int cc = 0; cc < 4; cc++) acc[a][b][cc] = 0.f;

    float4 ra[2], rb[2];
    auto ldgT = [&](int k0) {
        #pragma unroll
        for (int j = 0; j < 2; j++) {
            int id = tid + j*256;
            int mm = id >> 2, kc = (id & 3)*4;
            ra[j] = *(const float4*)(A + (long long)(m0+mm)*lda + k0 + kc);
            rb[j] = *(const float4*)(B + (long long)(n0+mm)*ldb + k0 + kc);
        }
    };
    auto stsT = [&](int st) {
        #pragma unroll
        for (int j = 0; j < 2; j++) {
            int id = tid + j*256;
            int mm = id >> 2, kc = (id & 3)*4;
            __nv_bfloat162* da = (__nv_bfloat162*)&As[st][mm][kc];
            da[0] = __float22bfloat162_rn(make_float2(ra[j].x, ra[j].y));
            da[1] = __float22bfloat162_rn(make_float2(ra[j].z, ra[j].w));
            __nv_bfloat162* db = (__nv_bfloat162*)&Bs[st][mm][kc];
            db[0] = __float22bfloat162_rn(make_float2(rb[j].x, rb[j].y));
            db[1] = __float22bfloat162_rn(make_float2(rb[j].z, rb[j].w));
        }
    };

    int nk = K >> 4;
    ldgT(0);
    stsT(0);
    __syncthreads();

    int r = lane >> 2, c = lane & 3;
    for (int kt = 0; kt < nk; kt++) {
        int cur = kt & 1;
        if (kt + 1 < nk) ldgT((kt+1)*16);
        uint32_t af[2][4];
        #pragma unroll
        for (int mt = 0; mt < 2; mt++) {
            int mb = wm*32 + mt*16;
            af[mt][0] = *(const uint32_t*)&As[cur][mb+r  ][c*2];
            af[mt][1] = *(const uint32_t*)&As[cur][mb+r+8][c*2];
            af[mt][2] = *(const uint32_t*)&As[cur][mb+r  ][c*2+8];
            af[mt][3] = *(const uint32_t*)&As[cur][mb+r+8][c*2+8];
        }
        #pragma unroll
        for (int nt = 0; nt < 8; nt++) {
            int nb = wn*64 + nt*8;
            uint32_t b0 = *(const uint32_t*)&Bs[cur][nb+r][c*2];
            uint32_t b1 = *(const uint32_t*)&Bs[cur][nb+r][c*2+8];
            #pragma unroll
            for (int mt = 0; mt < 2; mt++) {
                asm volatile(
                    "mma.sync.aligned.m16n8k16.row.col.f32.bf16.bf16.f32 "
                    "{%0,%1,%2,%3}, {%4,%5,%6,%7}, {%8,%9}, {%0,%1,%2,%3};"
                    : "+f"(acc[mt][nt][0]), "+f"(acc[mt][nt][1]),
                      "+f"(acc[mt][nt][2]), "+f"(acc[mt][nt][3])
                    : "r"(af[mt][0]), "r"(af[mt][1]), "r"(af[mt][2]), "r"(af[mt][3]),
                      "r"(b0), "r"(b1));
            }
        }
        if (kt + 1 < nk) stsT(cur ^ 1);
        __syncthreads();
    }
    int c2 = (lane & 3)*2;
    #pragma unroll
    for (int mt = 0; mt < 2; mt++) {
        #pragma unroll
        for (int nt = 0; nt < 8; nt++) {
            int row = m0 + wm*32 + mt*16 + r;
            int col = n0 + wn*64 + nt*8 + c2;
            float bv0 = bias ? bias[col] : 0.f;
            float bv1 = bias ? bias[col+1] : 0.f;
            float v0 = alpha*acc[mt][nt][0] + bv0;
            float v1 = alpha*acc[mt][nt][1] + bv1;
            float v2 = alpha*acc[mt][nt][2] + bv0;
            float v3 = alpha*acc[mt][nt][3] + bv1;
            if (RELU) { v0=fmaxf(v0,0.f); v1=fmaxf(v1,0.f); v2=fmaxf(v2,0.f); v3=fmaxf(v3,0.f); }
            C[(long long)row*ldc + col]       = v0;
            C[(long long)row*ldc + col+1]     = v1;
            C[(long long)(row+8)*ldc + col]   = v2;
            C[(long long)(row+8)*ldc + col+1] = v3;
        }
    }
}

// ---------- TF32 tensor-core GEMM (kept for pinv chain / NN shapes / attn2) ----------
template<int TB, int RELU, int BN, int DB>
__global__ void __launch_bounds__(256) tk(
    const float* __restrict__ A, const float* __restrict__ B,
    float* __restrict__ C, const float* __restrict__ bias,
    int M, int N, int K, int lda, int ldb, int ldc, float alpha, float cd,
    int zm, long long sa1, long long sa2, long long sb1, long long sb2,
    long long sc1, long long sc2)
{
    int z = blockIdx.z, z1 = z % zm, z2 = z / zm;
    A += (long long)z1*sa1 + (long long)z2*sa2;
    B += (long long)z1*sb1 + (long long)z2*sb2;
    C += (long long)z1*sc1 + (long long)z2*sc2;

    __shared__ float As[2][128][20];
    constexpr int BS_R = TB ? BN : 16;
    constexpr int BS_C = TB ? 20 : (BN + 8);
    __shared__ float Bs[2][BS_R][BS_C];
    constexpr int NB4 = BN/64;

    int tid = threadIdx.x, lane = tid & 31, warp = tid >> 5;
    int wm = warp & 3, wn = warp >> 2;
    constexpr int WN = BN/2, NT = WN/8;
    int m0 = blockIdx.y*128, n0 = blockIdx.x*BN;

    float acc[2][NT][4];
    #pragma unroll
    for (int a = 0; a < 2; a++)
        #pragma unroll
        for (int b = 0; b < NT; b++)
            #pragma unroll
            for (int cc = 0; cc < 4; cc++) acc[a][b][cc] = 0.f;

    float4 ra[2], rb[NB4];
    auto ldgT = [&](int k0) {
        #pragma unroll
        for (int j = 0; j < 2; j++) {
            int id = tid + j*256;
            int mm = id >> 2, kc = (id & 3)*4;
            ra[j] = *(const float4*)(A + (long long)(m0+mm)*lda + k0 + kc);
        }
        if (TB) {
            #pragma unroll
            for (int j = 0; j < NB4; j++) {
                int id = tid + j*256;
                int nn = id >> 2, kc = (id & 3)*4;
                rb[j] = *(const float4*)(B + (long long)(n0+nn)*ldb + k0 + kc);
            }
        } else {
            #pragma unroll
            for (int j = 0; j < NB4; j++) {
                int id = tid + j*256;
                int kk = id / (BN/4), nc = (id % (BN/4))*4;
                rb[j] = *(const float4*)(B + (long long)(k0+kk)*ldb + n0 + nc);
            }
        }
    };
    auto stsT = [&](int st) {
        #pragma unroll
        for (int j = 0; j < 2; j++) {
            int id = tid + j*256;
            int mm = id >> 2, kc = (id & 3)*4;
            *(float4*)&As[st][mm][kc] = ra[j];
        }
        if (TB) {
            #pragma unroll
            for (int j = 0; j < NB4; j++) {
                int id = tid + j*256;
                int nn = id >> 2, kc = (id & 3)*4;
                *(float4*)&Bs[st][nn][kc] = rb[j];
            }
        } else {
            #pragma unroll
            for (int j = 0; j < NB4; j++) {
                int id = tid + j*256;
                int kk = id / (BN/4), nc = (id % (BN/4))*4;
                *(float4*)&Bs[st][kk][nc] = rb[j];
            }
        }
    };

    int nk = K >> 4;
    ldgT(0);
    stsT(0);
    __syncthreads();

    for (int kt = 0; kt < nk; kt++) {
        int cur = kt & 1;
        if (kt + 1 < nk) ldgT((kt+1)*16);
        int k0 = kt*16;
        int r = lane >> 2, c = lane & 3;
        #pragma unroll
        for (int ks = 0; ks < 2; ks++) {
            int kb = ks*8;
            uint32_t af[2][4];
            #pragma unroll
            for (int mt = 0; mt < 2; mt++) {
                int mb = wm*32 + mt*16;
                af[mt][0] = __float_as_uint(As[cur][mb+r  ][kb+c  ]);
                af[mt][1] = __float_as_uint(As[cur][mb+r+8][kb+c  ]);
                af[mt][2] = __float_as_uint(As[cur][mb+r  ][kb+c+4]);
                af[mt][3] = __float_as_uint(As[cur][mb+r+8][kb+c+4]);
            }
            #pragma unroll
            for (int nt = 0; nt < NT; nt++) {
                int nb = wn*WN + nt*8;
                uint32_t b0, b1;
                if (TB) {
                    b0 = __float_as_uint(Bs[cur][nb+r][kb+c  ]);
                    b1 = __float_as_uint(Bs[cur][nb+r][kb+c+4]);
                } else {
                    float f0 = Bs[cur][kb+c  ][nb+r];
                    float f1 = Bs[cur][kb+c+4][nb+r];
                    if (DB) {
                        int ng = n0 + nb + r;
                        f0 = ((k0+kb+c  ) == ng ? cd : 0.f) - f0;
                        f1 = ((k0+kb+c+4) == ng ? cd : 0.f) - f1;
                    }
                    b0 = __float_as_uint(f0);
                    b1 = __float_as_uint(f1);
                }
                #pragma unroll
                for (int mt = 0; mt < 2; mt++) {
                    asm volatile(
                        "mma.sync.aligned.m16n8k8.row.col.f32.tf32.tf32.f32 "
                        "{%0,%1,%2,%3}, {%4,%5,%6,%7}, {%8,%9}, {%0,%1,%2,%3};"
                        : "+f"(acc[mt][nt][0]), "+f"(acc[mt][nt][1]),
                          "+f"(acc[mt][nt][2]), "+f"(acc[mt][nt][3])
                        : "r"(af[mt][0]), "r"(af[mt][1]), "r"(af[mt][2]), "r"(af[mt][3]),
                          "r"(b0), "r"(b1));
                }
            }
        }
        if (kt + 1 < nk) stsT(cur ^ 1);
        __syncthreads();
    }
    int r = lane >> 2, c2 = (lane & 3)*2;
    #pragma unroll
    for (int mt = 0; mt < 2; mt++) {
        #pragma unroll
        for (int nt = 0; nt < NT; nt++) {
            int row = m0 + wm*32 + mt*16 + r;
            int col = n0 + wn*WN + nt*8 + c2;
            float bv0 = bias ? bias[col] : 0.f;
            float bv1 = bias ? bias[col+1] : 0.f;
            float v0 = alpha*acc[mt][nt][0] + bv0;
            float v1 = alpha*acc[mt][nt][1] + bv1;
            float v2 = alpha*acc[mt][nt][2] + bv0;
            float v3 = alpha*acc[mt][nt][3] + bv1;
            if (RELU) { v0=fmaxf(v0,0.f); v1=fmaxf(v1,0.f); v2=fmaxf(v2,0.f); v3=fmaxf(v3,0.f); }
            C[(long long)row*ldc + col]       = v0;
            C[(long long)row*ldc + col+1]     = v1;
            C[(long long)(row+8)*ldc + col]   = v2;
            C[(long long)(row+8)*ldc + col+1] = v3;
        }
    }
}

// ---------- small kernels ----------
__global__ void k_buildh(const float* __restrict__ fc1o, const float* __restrict__ cls) {
    long long idx = blockIdx.x*256ll + threadIdx.x;
    if (idx >= 2ll*NSEQ*DM) return;
    int c = (int)(idx % DM); long long r = idx / DM; int b = (int)(r / NSEQ); int i = (int)(r % NSEQ);
    float v;
    if (i == 0) v = cls[c];
    else { int t = i-1; if (t >= NTOK) t -= NTOK; v = fc1o[((long long)b*NTOK + t)*DM + c]; }
    d_h[idx] = v;
}

__global__ void k_lnpad(const float* __restrict__ w, const float* __restrict__ bia) {
    int r = blockIdx.x; int b = r / NPAD, rr = r % NPAD;
    float* o = d_xln + (long long)r*DM;
    int t = threadIdx.x;
    if (rr < PADF) { o[t] = 0.f; o[t+256] = 0.f; return; }
    const float* in = d_h + ((long long)b*NSEQ + rr - PADF)*DM;
    __shared__ float red[256];
    float v0 = in[t], v1 = in[t+256];
    red[t] = v0+v1; __syncthreads();
    for (int s = 128; s > 0; s >>= 1) { if (t < s) red[t] += red[t+s]; __syncthreads(); }
    float mu = red[0]*(1.f/DM); __syncthreads();
    float e0 = v0-mu, e1 = v1-mu;
    red[t] = e0*e0+e1*e1; __syncthreads();
    for (int s = 128; s > 0; s >>= 1) { if (t < s) red[t] += red[t+s]; __syncthreads(); }
    float rstd = rsqrtf(red[0]*(1.f/DM) + 1e-5f);
    o[t]     = e0*rstd*w[t]     + bia[t];
    o[t+256] = e1*rstd*w[t+256] + bia[t+256];
}

__global__ void k_splitqkv4() {
    long long idx = blockIdx.x*256ll + threadIdx.x;            // over float4s
    if (idx >= 2ll*NPAD*DM/4) return;
    int c4 = (int)(idx % 128);                                 // float4 within 512
    long long bn = idx / 128;
    int hh = c4 >> 4, d4 = c4 & 15;
    int b = (int)(bn / NPAD), n = (int)(bn % NPAD);
    const float4* src = (const float4*)(d_qkv + bn*QW) + c4;
    long long dst = (((long long)(b*8+hh)*NPAD) + n)*(HD/4) + d4;
    ((float4*)d_q)[dst] = src[0];
    ((float4*)d_k)[dst] = src[DM/4];
    ((float4*)d_v)[dst] = src[2*DM/4];
}

__global__ void k_lm() {
    int z = blockIdx.y, j = blockIdx.x, dd = threadIdx.x;
    const float* q = d_q + ((long long)z*NPAD + j*64)*HD + dd;
    const float* k = d_k + ((long long)z*NPAD + j*64)*HD + dd;
    float sq = 0.f, sk = 0.f;
    #pragma unroll 8
    for (int i = 0; i < 64; i++) { sq += q[i*HD]; sk += k[i*HD]; }
    d_ql[(z*NLM+j)*HD+dd] = sq*(1.f/64.f);
    d_kl[(z*NLM+j)*HD+dd] = sk*(1.f/64.f);
}

// softmax over rows of 16384: 512 threads, register-cached (1 read + 1 write)
__global__ void __launch_bounds__(512) k_sm16k(float* __restrict__ p) {
    float4* p4 = (float4*)(p + (long long)blockIdx.x * NPAD);
    int t = threadIdx.x;
    __shared__ float red[512];
    float4 va[8];
    float m = -1e30f;
    #pragma unroll
    for (int j = 0; j < 8; j++) {
        va[j] = p4[t + j*512];
        m = fmaxf(m, fmaxf(fmaxf(va[j].x, va[j].y), fmaxf(va[j].z, va[j].w)));
    }
    red[t] = m; __syncthreads();
    for (int s = 256; s > 0; s >>= 1) { if (t < s) red[t] = fmaxf(red[t], red[t+s]); __syncthreads(); }
    m = red[0]; __syncthreads();
    float sum = 0.f;
    #pragma unroll
    for (int j = 0; j < 8; j++) {
        va[j].x = __expf(va[j].x - m); va[j].y = __expf(va[j].y - m);
        va[j].z = __expf(va[j].z - m); va[j].w = __expf(va[j].w - m);
        sum += (va[j].x + va[j].y) + (va[j].z + va[j].w);
    }
    red[t] = sum; __syncthreads();
    for (int s = 256; s > 0; s >>= 1) { if (t < s) red[t] += red[t+s]; __syncthreads(); }
    float inv = 1.f/red[0];
    #pragma unroll
    for (int j = 0; j < 8; j++) {
        va[j].x *= inv; va[j].y *= inv; va[j].z *= inv; va[j].w *= inv;
        p4[t + j*512] = va[j];
    }
}

// softmax over rows of 256: one warp per row, shfl reductions (1 read + 1 write)
__global__ void k_sm256w(float* __restrict__ p, long long nrows) {
    long long row = blockIdx.x*8ll + (threadIdx.x >> 5);
    if (row >= nrows) return;
    int lane = threadIdx.x & 31;
    float4* p4 = (float4*)(p + row*NLM);
    float4 u0 = p4[lane], u1 = p4[lane+32];
    float m = fmaxf(fmaxf(fmaxf(u0.x,u0.y),fmaxf(u0.z,u0.w)),
                    fmaxf(fmaxf(u1.x,u1.y),fmaxf(u1.z,u1.w)));
    #pragma unroll
    for (int s = 16; s > 0; s >>= 1) m = fmaxf(m, __shfl_xor_sync(0xffffffffu, m, s));
    u0.x=__expf(u0.x-m); u0.y=__expf(u0.y-m); u0.z=__expf(u0.z-m); u0.w=__expf(u0.w-m);
    u1.x=__expf(u1.x-m); u1.y=__expf(u1.y-m); u1.z=__expf(u1.z-m); u1.w=__expf(u1.w-m);
    float sum = (u0.x+u0.y)+(u0.z+u0.w)+(u1.x+u1.y)+(u1.z+u1.w);
    #pragma unroll
    for (int s = 16; s > 0; s >>= 1) sum += __shfl_xor_sync(0xffffffffu, sum, s);
    float inv = 1.f/sum;
    u0.x*=inv; u0.y*=inv; u0.z*=inv; u0.w*=inv;
    u1.x*=inv; u1.y*=inv; u1.z*=inv; u1.w*=inv;
    p4[lane] = u0; p4[lane+32] = u1;
}

__global__ void k_init() { d_sc[0] = 0; d_sc[1] = 0; }

__global__ void k_rmax() {
    int mb = blockIdx.x >> 8, i = blockIdx.x & 255, t = threadIdx.x;
    __shared__ float red[256];
    red[t] = fabsf(d_a2[((long long)mb*256+i)*256 + t]); __syncthreads();
    for (int s = 128; s > 0; s >>= 1) { if (t < s) red[t] += red[t+s]; __syncthreads(); }
    if (t == 0) atomicMax(&d_sc[0], __float_as_int(red[0]));
}

__global__ void k_cmax() {
    int mb = blockIdx.x, j = threadIdx.x;
    float s = 0.f;
    for (int i = 0; i < 256; i++) s += fabsf(d_a2[((long long)mb*256+i)*256 + j]);
    atomicMax(&d_sc[1], __float_as_int(s));
}

__global__ void k_tz() {
    long long idx = blockIdx.x*256ll + threadIdx.x;
    if (idx >= (long long)BH*65536) return;
    int mb = (int)(idx >> 16); int r = (int)((idx >> 8) & 255); int c = (int)(idx & 255);
    float sc = __int_as_float(d_sc[0]) * __int_as_float(d_sc[1]);
    d_z[idx] = d_a2[(long long)mb*65536 + (long long)c*256 + r] / sc;
}

__global__ void k_red() {
    int idx = blockIdx.x*256 + threadIdx.x;
    if (idx >= BH*NLM*HD) return;
    float s = 0.f;
    #pragma unroll
    for (int p = 0; p < NSPL; p++) s += d_part[(long long)p*BH*NLM*HD + idx];
    d_t3[idx] = s;
}

__global__ void k_dw(const float* __restrict__ w) {
    int z = blockIdx.y; int b = z >> 3, hh = z & 7;
    int i = blockIdx.x*4 + threadIdx.y;
    int dd = threadIdx.x;
    const float* v = d_v + (long long)z*NPAD*HD + dd;
    float s = 0.f;
    #pragma unroll
    for (int tp = 0; tp < 33; tp++) {
        int ii = i + tp - 16;
        if (ii >= 0 && ii < NPAD) s += w[hh*33+tp] * v[(long long)ii*HD];
    }
    d_ao[((long long)b*NPAD + i)*DM + hh*HD + dd] += s;
}

__global__ void k_radd() {
    long long idx = blockIdx.x*256ll + threadIdx.x;
    if (idx >= 2ll*NSEQ*DM) return;
    int c = (int)(idx % DM); long long r = idx / DM; int b = (int)(r / NSEQ); int i = (int)(r % NSEQ);
    d_h[idx] += d_xln[((long long)b*NPAD + PADF + i)*DM + c];
}

__global__ void k_ppeg(const float* __restrict__ w7, const float* __restrict__ b7,
                       const float* __restrict__ w5, const float* __restrict__ b5,
                       const float* __restrict__ w3, const float* __restrict__ b3) {
    int p = blockIdx.x, b = blockIdx.y, c = threadIdx.x;
    int r = p / GR, ww = p % GR;
    const float* base = d_h + ((long long)b*NSEQ + 1)*DM + c;
    float acc = base[(long long)p*DM] + b7[c] + b5[c] + b3[c];
    for (int i = 0; i < 7; i++) {
        int rr = r + i - 3; if (rr < 0 || rr >= GR) continue;
        for (int j = 0; j < 7; j++) {
            int cc = ww + j - 3; if (cc < 0 || cc >= GR) continue;
            float x = base[(long long)(rr*GR+cc)*DM];
            acc += w7[c*49 + i*7 + j] * x;
            if (i >= 1 && i < 6 && j >= 1 && j < 6) acc += w5[c*25 + (i-1)*5 + (j-1)] * x;
            if (i >= 2 && i < 5 && j >= 2 && j < 5) acc += w3[c*9 + (i-2)*3 + (j-2)] * x;
        }
    }
    d_xln[((long long)b*NFEAT + p)*DM + c] = acc;
}

__global__ void k_ppcp() {
    long long idx = blockIdx.x*256ll + threadIdx.x;
    if (idx >= 2ll*NFEAT*DM) return;
    int c = (int)(idx % DM); long long r = idx / DM; int b = (int)(r / NFEAT); int p = (int)(r % NFEAT);
    d_h[((long long)b*NSEQ + 1 + p)*DM + c] = d_xln[idx];
}

__global__ void k_head(const float* __restrict__ nw, const float* __restrict__ nb,
                       const float* __restrict__ f2w, const float* __restrict__ f2b,
                       float* __restrict__ out) {
    int b = blockIdx.x, t = threadIdx.x;
    const float* x = d_h + (long long)b*NSEQ*DM;
    __shared__ float red[256];
    float v0 = x[t], v1 = x[t+256];
    red[t] = v0+v1; __syncthreads();
    for (int s = 128; s > 0; s >>= 1) { if (t < s) red[t] += red[t+s]; __syncthreads(); }
    float mu = red[0]*(1.f/DM); __syncthreads();
    float e0 = v0-mu, e1 = v1-mu;
    red[t] = e0*e0+e1*e1; __syncthreads();
    for (int s = 128; s > 0; s >>= 1) { if (t < s) red[t] += red[t+s]; __syncthreads(); }
    float rstd = rsqrtf(red[0]*(1.f/DM) + 1e-5f);
    __syncthreads();
    float n0 = e0*rstd*nw[t] + nb[t], n1 = e1*rstd*nw[t+256] + nb[t+256];
    for (int j = 0; j < 2; j++) {
        red[t] = n0*f2w[j*DM+t] + n1*f2w[j*DM+t+256]; __syncthreads();
        for (int s = 128; s > 0; s >>= 1) { if (t < s) red[t] += red[t+s]; __syncthreads(); }
        if (t == 0) out[b*2+j] = red[0] + f2b[j];
        __syncthreads();
    }
}

// ---------- host wrappers ----------
static inline void HK(int RELU, const float* A, const float* B, float* C, const float* bias,
                      int M, int N, int K, int lda, int ldb, int ldc, float al,
                      int Z, int zm,
                      long long a1, long long a2, long long b1, long long b2,
                      long long c1, long long c2) {
    dim3 g(N/128, M/128, Z);
    if (RELU) hk<1><<<g,256>>>(A,B,C,bias,M,N,K,lda,ldb,ldc,al,zm,a1,a2,b1,b2,c1,c2);
    else      hk<0><<<g,256>>>(A,B,C,bias,M,N,K,lda,ldb,ldc,al,zm,a1,a2,b1,b2,c1,c2);
}
static inline void TK(int TB, int RELU, int DB,
                      const float* A, const float* B, float* C, const float* bias,
                      int M, int N, int K, int lda, int ldb, int ldc, float al, float cd,
                      int Z, int zm,
                      long long a1, long long a2, long long b1, long long b2,
                      long long c1, long long c2) {
    if (N % 128 == 0) {
        dim3 g(N/128, M/128, Z);
        if (TB && RELU) tk<1,1,128,0><<<g,256>>>(A,B,C,bias,M,N,K,lda,ldb,ldc,al,cd,zm,a1,a2,b1,b2,c1,c2);
        else if (TB)    tk<1,0,128,0><<<g,256>>>(A,B,C,bias,M,N,K,lda,ldb,ldc,al,cd,zm,a1,a2,b1,b2,c1,c2);
        else if (DB)    tk<0,0,128,1><<<g,256>>>(A,B,C,bias,M,N,K,lda,ldb,ldc,al,cd,zm,a1,a2,b1,b2,c1,c2);
        else            tk<0,0,128,0><<<g,256>>>(A,B,C,bias,M,N,K,lda,ldb,ldc,al,cd,zm,a1,a2,b1,b2,c1,c2);
    } else {
        dim3 g(N/64, M/128, Z);
        tk<0,0,64,0><<<g,256>>>(A,B,C,bias,M,N,K,lda,ldb,ldc,al,cd,zm,a1,a2,b1,b2,c1,c2);
    }
}

extern "C" void kernel_launch(void* const* d_in, const int* in_sizes, int n_in,
                              void* d_out, int out_size) {
    const float* x    = (const float*)d_in[0];
    const float* fc1w = (const float*)d_in[1];
    const float* fc1b = (const float*)d_in[2];
    const float* cls  = (const float*)d_in[3];
    const float* lnw  = (const float*)d_in[4];
    const float* lnb  = (const float*)d_in[5];
    const float* qkvw = (const float*)d_in[6];
    const float* qkvb = (const float*)d_in[7];
    const float* aow  = (const float*)d_in[8];
    const float* aob  = (const float*)d_in[9];
    const float* rcw  = (const float*)d_in[10];
    const float* w7 = (const float*)d_in[11]; const float* b7 = (const float*)d_in[12];
    const float* w5 = (const float*)d_in[13]; const float* b5 = (const float*)d_in[14];
    const float* w3 = (const float*)d_in[15]; const float* b3 = (const float*)d_in[16];
    const float* nw = (const float*)d_in[17]; const float* nb = (const float*)d_in[18];
    const float* f2w = (const float*)d_in[19]; const float* f2b = (const float*)d_in[20];
    float* out = (float*)d_out;

    float *xln, *qkv, *sbuf, *ao, *q, *k, *v, *part;
    float *ql, *kl, *a2, *z, *z2, *az, *tt, *uu, *t3, *w;
    cudaGetSymbolAddress((void**)&xln, d_xln);
    cudaGetSymbolAddress((void**)&qkv, d_qkv);
    cudaGetSymbolAddress((void**)&sbuf, d_sbuf);
    cudaGetSymbolAddress((void**)&ao, d_ao);
    cudaGetSymbolAddress((void**)&q, d_q);
    cudaGetSymbolAddress((void**)&k, d_k);
    cudaGetSymbolAddress((void**)&v, d_v);
    cudaGetSymbolAddress((void**)&part, d_part);
    cudaGetSymbolAddress((void**)&ql, d_ql);
    cudaGetSymbolAddress((void**)&kl, d_kl);
    cudaGetSymbolAddress((void**)&a2, d_a2);
    cudaGetSymbolAddress((void**)&z, d_z);
    cudaGetSymbolAddress((void**)&z2, d_z2);
    cudaGetSymbolAddress((void**)&az, d_az);
    cudaGetSymbolAddress((void**)&tt, d_tt);
    cudaGetSymbolAddress((void**)&uu, d_uu);
    cudaGetSymbolAddress((void**)&t3, d_t3);
    cudaGetSymbolAddress((void**)&w, d_w);

    const long long SQ  = (long long)NPAD*QW;
    const long long SD  = (long long)NPAD*DM;
    const long long SH  = (long long)NPAD*HD;
    const long long SS3 = (long long)NLM*NPAD;
    const long long SS1 = (long long)NPAD*NLM;

    // fc1 + relu (bf16) -> sbuf (32000,512); then assemble token stream h
    HK(1, x, fc1w, sbuf, fc1b, 2*NTOK, DM, 1024, 1024, 1024, DM, 1.f, 1,1, 0,0,0,0,0,0);
    k_buildh<<<(int)((2ll*NSEQ*DM+255)/256),256>>>(sbuf, cls);

    for (int l = 0; l < 2; l++) {
        k_lnpad<<<2*NPAD,256>>>(lnw + l*DM, lnb + l*DM);
        HK(0, xln, qkvw + (long long)l*QW*DM, qkv, qkvb + l*QW,
           NPAD, QW, DM, DM, DM, QW, 1.f, 2,2, SD,0, 0,0, SQ,0);
        k_splitqkv4<<<(int)((2ll*NPAD*DM/4+255)/256),256>>>();
        k_lm<<<dim3(256,16),64>>>();
        // attn2 = softmax(0.125 * ql @ kl^T)  (TF32)
        TK(1,0,0, ql, kl, a2, 0, NLM, NLM, HD, HD, HD, NLM, 0.125f, 0.f, BH,BH,
           NLM*HD,0, NLM*HD,0, NLM*NLM,0);
        k_sm256w<<<(int)((BH*NLM+7)/8),256>>>(a2, (long long)BH*NLM);
        // pinv(attn2) (TF32, elementwise fused into B fragment loads)
        k_init<<<1,1>>>();
        k_rmax<<<BH*NLM,256>>>();
        k_cmax<<<BH,256>>>();
        k_tz<<<(BH*65536+255)/256,256>>>();
        float* zc = z; float* zn = z2;
        for (int it = 0; it < 6; it++) {
            TK(0,0,0, a2, zc, az, 0, NLM,NLM,NLM, NLM,NLM,NLM, 1.f, 0.f, BH,BH, 65536,0,65536,0,65536,0);
            TK(0,0,1, az, az, tt, 0, NLM,NLM,NLM, NLM,NLM,NLM, 1.f, 7.f, BH,BH, 65536,0,65536,0,65536,0);
            TK(0,0,1, az, tt, uu, 0, NLM,NLM,NLM, NLM,NLM,NLM, 1.f, 15.f, BH,BH, 65536,0,65536,0,65536,0);
            TK(0,0,1, zc, uu, zn, 0, NLM,NLM,NLM, NLM,NLM,NLM, 0.25f, 13.f, BH,BH, 65536,0,65536,0,65536,0);
            float* sw = zc; zc = zn; zn = sw;
        }
        // S3 = softmax(0.125 * ql @ k^T)   [z][256][16384]  (bf16 GEMM)
        HK(0, ql, k, sbuf, 0, NLM, NPAD, HD, HD, HD, NPAD, 0.125f, BH,BH,
           NLM*HD,0, SH,0, SS3,0);
        k_sm16k<<<BH*NLM,512>>>(sbuf);
        // t3 = S3 @ v  split-K over 32 chunks (TF32)
        TK(0,0,0, sbuf, v, part, 0, NLM, HD, KSPL, NPAD, HD, HD, 1.f, 0.f, BH*NSPL, BH,
           SS3, 512, SH, (long long)KSPL*HD, (long long)NLM*HD, (long long)BH*NLM*HD);
        k_red<<<(BH*NLM*HD+255)/256,256>>>();
        // w = pinv @ t3  (TF32)
        TK(0,0,0, zc, t3, w, 0, NLM, HD, NLM, NLM, HD, HD, 1.f, 0.f, BH,BH,
           65536,0, NLM*HD,0, NLM*HD,0);
        // S1 = softmax(0.125 * q @ kl^T)  [z][16384][256]  (bf16 GEMM)
        HK(0, q, kl, sbuf, 0, NPAD, NLM, HD, HD, HD, NLM, 0.125f, BH,BH,
           SH,0, NLM*HD,0, SS1,0);
        k_sm256w<<<(int)(((long long)BH*NPAD+7)/8),256>>>(sbuf, (long long)BH*NPAD);
        // ao = S1 @ w  -> [b][n][h*64+d]  (TF32)
        TK(0,0,0, sbuf, w, ao, 0, NPAD, HD, NLM, NLM, HD, DM, 1.f, 0.f, BH,8,
           SS1, 8ll*SS1, NLM*HD, 8ll*NLM*HD, HD, SD);
        // depthwise residual conv over v
        k_dw<<<dim3(NPAD/4,BH),dim3(64,4)>>>(rcw + l*264);
        // out projection + residual  (bf16 GEMM)
        HK(0, ao, aow + (long long)l*DM*DM, xln, aob + l*DM,
           NPAD, DM, DM, DM, DM, DM, 1.f, 2,2, SD,0, 0,0, SD,0);
        k_radd<<<(int)((2ll*NSEQ*DM+255)/256),256>>>();
        if (l == 0) {
            k_ppeg<<<dim3(NFEAT,2),512>>>(w7,b7,w5,b5,w3,b3);
            k_ppcp<<<(int)((2ll*NFEAT*DM+255)/256),256>>>();
        }
    }
    k_head<<<2,256>>>(nw, nb, f2w, f2b, out);
}